// round 2
// baseline (speedup 1.0000x reference)
#include <cuda_runtime.h>
#include <math.h>

#define Bz 32
#define Dd 768
#define D3 2304
#define Xx 256
#define VV 30522
#define VP 30592   // 239*128 padded vocab
#define Jj 4
#define Kk 8

// ---------------- persistent device scratch (no allocations allowed) ----------------
__device__ float g_h[Bz * Dd];
__device__ float g_x[Bz * Dd];
__device__ float g_gi[Bz * D3];
__device__ float g_gh[Bz * D3];
__device__ float g_attn[Bz * Xx];
__device__ float g_pgen[Bz];
__device__ float g_e[Bz * VP];

// ---------------- packed f32x2 helpers ----------------
__device__ __forceinline__ unsigned long long pk2(float x, float y) {
    unsigned long long r;
    asm("mov.b64 %0, {%1, %2};" : "=l"(r) : "f"(x), "f"(y));
    return r;
}
__device__ __forceinline__ void upk2(unsigned long long v, float& x, float& y) {
    asm("mov.b64 {%0, %1}, %2;" : "=f"(x), "=f"(y) : "l"(v));
}
__device__ __forceinline__ unsigned long long fma2(unsigned long long a,
                                                   unsigned long long b,
                                                   unsigned long long c) {
    unsigned long long d;
    asm("fma.rn.f32x2 %0, %1, %2, %3;" : "=l"(d) : "l"(a), "l"(b), "l"(c));
    return d;
}
__device__ __forceinline__ float sigf(float x) { return 1.0f / (1.0f + expf(-x)); }

// ---------------- init: h <- hidden[0] ----------------
__global__ void init_kernel(const float* __restrict__ hidden) {
    int i = blockIdx.x * 256 + threadIdx.x;
    if (i < Bz * Dd) g_h[i] = hidden[i];
}

// ---------------- K1: gate GEMMs gi = x@w_ih^T + b_ih ; gh = h@w_hh^T + b_hh -------
// grid (72,2), block 256. Tile 32 rows(b) x 32 cols(c), thread = 1 col x 4 rows.
__global__ void k1_kernel(const float* __restrict__ dec,
                          const float* __restrict__ w_ih, const float* __restrict__ w_hh,
                          const float* __restrict__ b_ih, const float* __restrict__ b_hh,
                          int j, int k0) {
    __shared__ float As[32][36];   // [k][b], padded for LDS.128 alignment
    __shared__ float Ws[32][33];   // [k][c]
    int t = threadIdx.x;
    int lane = t & 31, wr = t >> 5;
    int cbase = blockIdx.x * 32;

    const float* A; int lda; const float* W; const float* bias; float* O;
    if (blockIdx.y == 0) {
        A = k0 ? (dec + (size_t)j * Dd) : g_x;
        lda = k0 ? (Jj * Dd) : Dd;
        W = w_ih; bias = b_ih; O = g_gi;
    } else {
        A = g_h; lda = Dd; W = w_hh; bias = b_hh; O = g_gh;
    }

    int c = lane, bq = wr;
    float acc[4] = {0.f, 0.f, 0.f, 0.f};
    for (int kb = 0; kb < Dd; kb += 32) {
        __syncthreads();
        for (int r = wr; r < 32; r += 8) {
            As[lane][r] = A[(size_t)r * lda + kb + lane];
            Ws[lane][r] = W[(size_t)(cbase + r) * Dd + kb + lane];
        }
        __syncthreads();
        #pragma unroll
        for (int kk = 0; kk < 32; kk++) {
            float w = Ws[kk][c];
            float4 a = *(const float4*)&As[kk][bq * 4];
            acc[0] += a.x * w; acc[1] += a.y * w;
            acc[2] += a.z * w; acc[3] += a.w * w;
        }
    }
    float bb = bias[cbase + c];
    #pragma unroll
    for (int i = 0; i < 4; i++)
        O[(size_t)(bq * 4 + i) * D3 + cbase + c] = acc[i] + bb;
}

// ---------------- K2: h update; attention softmax; context; p_gen ----------------
// grid 32 (one block per batch row), block 256.
__global__ void k2_kernel(const float* __restrict__ dec, const float* __restrict__ enc,
                          const int* __restrict__ ids,
                          const float* __restrict__ w_gen, const float* __restrict__ b_gen,
                          int j, int k0) {
    __shared__ float hs[Dd];
    __shared__ float sc[Xx];
    __shared__ float red[256];
    int b = blockIdx.x, t = threadIdx.x;
    const float* gi = g_gi + (size_t)b * D3;
    const float* gh = g_gh + (size_t)b * D3;

    for (int d = t; d < Dd; d += 256) {
        float r = sigf(gi[d] + gh[d]);
        float z = sigf(gi[Dd + d] + gh[Dd + d]);
        float n = tanhf(gi[2 * Dd + d] + r * gh[2 * Dd + d]);
        float h = (1.f - z) * n + z * g_h[(size_t)b * Dd + d];
        hs[d] = h;
        g_h[(size_t)b * Dd + d] = h;
    }
    __syncthreads();

    int lane = t & 31, wr = t >> 5;
    for (int xi = wr; xi < Xx; xi += 8) {
        const float* er = enc + ((size_t)b * Xx + xi) * Dd;
        float s = 0.f;
        for (int kk = lane; kk < Dd; kk += 32) s += er[kk] * hs[kk];
        #pragma unroll
        for (int o = 16; o; o >>= 1) s += __shfl_xor_sync(0xffffffffu, s, o);
        if (lane == 0) sc[xi] = (ids[b * Xx + xi] == 0) ? -1e9f : s;
    }
    __syncthreads();

    // softmax over sc[256] (max-subtracted)
    red[t] = sc[t]; __syncthreads();
    for (int s2 = 128; s2; s2 >>= 1) { if (t < s2) red[t] = fmaxf(red[t], red[t + s2]); __syncthreads(); }
    float m = red[0]; __syncthreads();
    float ev = expf(sc[t] - m);
    red[t] = ev; __syncthreads();
    for (int s2 = 128; s2; s2 >>= 1) { if (t < s2) red[t] += red[t + s2]; __syncthreads(); }
    float inv = 1.f / red[0];
    __syncthreads();
    float at = ev * inv;
    sc[t] = at;
    g_attn[b * Xx + t] = at;
    __syncthreads();

    // context + p_gen dot:  w_gen[0:768].h + w_gen[768:1536].x + w_gen[1536:2304].ctx
    const float* xr = k0 ? (dec + ((size_t)b * Jj + j) * Dd) : (g_x + (size_t)b * Dd);
    float pg = 0.f;
    for (int d = t; d < Dd; d += 256) {
        float cx = 0.f;
        const float* eb = enc + (size_t)b * Xx * Dd + d;
        #pragma unroll 4
        for (int x2 = 0; x2 < Xx; x2++) cx += sc[x2] * eb[(size_t)x2 * Dd];
        pg += w_gen[2 * Dd + d] * cx + w_gen[d] * hs[d] + w_gen[Dd + d] * xr[d];
    }
    red[t] = pg; __syncthreads();
    for (int s2 = 128; s2; s2 >>= 1) { if (t < s2) red[t] += red[t + s2]; __syncthreads(); }
    if (t == 0) g_pgen[b] = sigf(red[0] + b_gen[0]);
}

// ---------------- K3: e = exp(h @ emb^T), padded vocab; packed f32x2 GEMM ----------
// grid 239, block 256. Tile 128 v x 32 b; thread = 4 v x 4 b.
__global__ void k3_kernel(const float* __restrict__ emb) {
    __shared__ float Es[32][132];  // [k][v]
    __shared__ float Hs[32][36];   // [k][b]
    int t = threadIdx.x;
    int lane = t & 31, wr = t >> 5;
    int vbase = blockIdx.x * 128;
    int vq = t & 31, bq = t >> 5;

    unsigned long long acc[8];
    #pragma unroll
    for (int i = 0; i < 8; i++) acc[i] = 0ull;

    for (int kb = 0; kb < Dd; kb += 32) {
        __syncthreads();
        for (int r = wr; r < 128; r += 8) {
            int v = vbase + r;
            Es[lane][r] = (v < VV) ? emb[(size_t)v * Dd + kb + lane] : 0.f;
        }
        for (int r = wr; r < 32; r += 8)
            Hs[lane][r] = g_h[(size_t)r * Dd + kb + lane];
        __syncthreads();
        #pragma unroll
        for (int kk = 0; kk < 32; kk++) {
            float4 e4 = *(const float4*)&Es[kk][vq * 4];
            float4 h4 = *(const float4*)&Hs[kk][bq * 4];
            unsigned long long hp0 = pk2(h4.x, h4.y), hp1 = pk2(h4.z, h4.w);
            unsigned long long e0 = pk2(e4.x, e4.x), e1 = pk2(e4.y, e4.y);
            unsigned long long e2 = pk2(e4.z, e4.z), e3 = pk2(e4.w, e4.w);
            acc[0] = fma2(e0, hp0, acc[0]); acc[1] = fma2(e1, hp0, acc[1]);
            acc[2] = fma2(e2, hp0, acc[2]); acc[3] = fma2(e3, hp0, acc[3]);
            acc[4] = fma2(e0, hp1, acc[4]); acc[5] = fma2(e1, hp1, acc[5]);
            acc[6] = fma2(e2, hp1, acc[6]); acc[7] = fma2(e3, hp1, acc[7]);
        }
    }
    int v0 = vbase + vq * 4;
    #pragma unroll
    for (int bp = 0; bp < 2; bp++) {
        float lo[4], hi[4];
        #pragma unroll
        for (int vi = 0; vi < 4; vi++) upk2(acc[bp * 4 + vi], lo[vi], hi[vi]);
        int b0 = bq * 4 + bp * 2;
        float4 o0 = make_float4(expf(lo[0]), expf(lo[1]), expf(lo[2]), expf(lo[3]));
        float4 o1 = make_float4(expf(hi[0]), expf(hi[1]), expf(hi[2]), expf(hi[3]));
        *(float4*)&g_e[(size_t)b0 * VP + v0] = o0;
        *(float4*)&g_e[(size_t)(b0 + 1) * VP + v0] = o1;
    }
}

// ---------------- K5: rowsum + dense argmax; output write; scatter; argmax; x_next --
// grid 32, block 256.
__global__ void k5_kernel(const float* __restrict__ emb, const int* __restrict__ ids,
                          float* __restrict__ out, int j, int kstep) {
    __shared__ float redf[256];
    __shared__ unsigned long long redk[256];
    __shared__ float s_ids_attn[Xx];
    __shared__ int s_ids[Xx];
    __shared__ int s_amax;
    int b = blockIdx.x, t = threadIdx.x;
    const float* erow = g_e + (size_t)b * VP;

    // pass 1: sum of e, dense max key (first-index tie-break via ~v)
    float sum = 0.f; unsigned long long mk = 0ull;
    for (int v = t; v < VV; v += 256) {
        float e = erow[v];
        sum += e;
        unsigned long long key =
            ((unsigned long long)__float_as_uint(e) << 32) | (unsigned)(~v);
        if (key > mk) mk = key;
    }
    redf[t] = sum; redk[t] = mk; __syncthreads();
    for (int s2 = 128; s2; s2 >>= 1) {
        if (t < s2) {
            redf[t] += redf[t + s2];
            if (redk[t + s2] > redk[t]) redk[t] = redk[t + s2];
        }
        __syncthreads();
    }
    float inv = 1.f / redf[0];
    float pg = g_pgen[b];
    int vd = ~(unsigned)(redk[0] & 0xffffffffu);
    __syncthreads();

    // stage ids/attn rows in shared
    s_ids[t] = ids[b * Xx + t];
    s_ids_attn[t] = g_attn[b * Xx + t];

    // pass 2: dense output write
    float* orow = out + (((size_t)b * Jj + j) * Kk + kstep) * VV;
    for (int v = t; v < VV; v += 256) orow[v] = pg * erow[v] * inv;
    __syncthreads();

    // scattered candidates: full value at the 256 id positions (dups identical)
    float one_m = 1.f - pg;
    float dval = pg * erow[vd] * inv;
    unsigned long long best =
        ((unsigned long long)__float_as_uint(dval) << 32) | (unsigned)(~vd);
    {
        int v = s_ids[t];
        float a = 0.f;
        #pragma unroll 4
        for (int x2 = 0; x2 < Xx; x2++) a += (s_ids[x2] == v) ? s_ids_attn[x2] : 0.f;
        float full = pg * erow[v] * inv + one_m * a;
        orow[v] = full;
        unsigned long long key =
            ((unsigned long long)__float_as_uint(full) << 32) | (unsigned)(~v);
        if (key > best) best = key;
    }
    redk[t] = best; __syncthreads();
    for (int s2 = 128; s2; s2 >>= 1) {
        if (t < s2 && redk[t + s2] > redk[t]) redk[t] = redk[t + s2];
        __syncthreads();
    }
    if (t == 0) s_amax = ~(unsigned)(redk[0] & 0xffffffffu);
    __syncthreads();
    int am = s_amax;
    for (int d = t; d < Dd; d += 256)
        g_x[(size_t)b * Dd + d] = emb[(size_t)am * Dd + d];
}

extern "C" void kernel_launch(void* const* d_in, const int* in_sizes, int n_in,
                              void* d_out, int out_size) {
    const float* dec    = (const float*)d_in[0];
    const float* hidden = (const float*)d_in[1];
    const float* enc    = (const float*)d_in[2];
    const int*   ids    = (const int*)  d_in[3];
    int ei = (in_sizes[4] <= 16) ? 5 : 4;   // skip max_len scalar if present
    const float* emb   = (const float*)d_in[ei + 0];
    const float* w_ih  = (const float*)d_in[ei + 1];
    const float* w_hh  = (const float*)d_in[ei + 2];
    const float* b_ih  = (const float*)d_in[ei + 3];
    const float* b_hh  = (const float*)d_in[ei + 4];
    const float* w_gen = (const float*)d_in[ei + 5];
    const float* b_gen = (const float*)d_in[ei + 6];
    float* out = (float*)d_out;

    init_kernel<<<(Bz * Dd + 255) / 256, 256>>>(hidden);
    for (int j = 0; j < Jj; j++) {
        for (int k = 0; k < Kk; k++) {
            int k0 = (k == 0);
            k1_kernel<<<dim3(72, 2), 256>>>(dec, w_ih, w_hh, b_ih, b_hh, j, k0);
            k2_kernel<<<Bz, 256>>>(dec, enc, ids, w_gen, b_gen, j, k0);
            k3_kernel<<<239, 256>>>(emb);
            k5_kernel<<<Bz, 256>>>(emb, ids, out, j, k);
        }
    }
}

// round 4
// speedup vs baseline: 1.6113x; 1.6113x over previous
#include <cuda_runtime.h>
#include <math.h>

#define Bz 32
#define Dd 768
#define D3 2304
#define Xx 256
#define VV 30522
#define VP 30720          // 120*256 padded vocab
#define NB 120            // K3 grid (v-blocks of 256)
#define BW 960            // bitmap words per batch row (30720/32)
#define Jj 4
#define Kk 8

// ---------------- persistent device scratch ----------------
__device__ float g_h[Bz * Dd];
__device__ float g_x[Bz * Dd];
__device__ float g_gi[Bz * D3];
__device__ float g_gh[Bz * D3];
__device__ float g_attn[Bz * Xx];
__device__ float g_pgen[Bz];
__device__ float g_inv[Bz];
__device__ __align__(16) float g_e[Bz * VP];
__device__ float g_psum[Bz * NB];
__device__ unsigned long long g_pkey[Bz * NB];
__device__ unsigned int g_bit[Bz * BW];   // id-position bitmap (set-only, idempotent)

// ---------------- packed f32x2 helpers ----------------
__device__ __forceinline__ void upk2(unsigned long long v, float& x, float& y) {
    asm("mov.b64 {%0, %1}, %2;" : "=f"(x), "=f"(y) : "l"(v));
}
__device__ __forceinline__ unsigned long long fma2(unsigned long long a,
                                                   unsigned long long b,
                                                   unsigned long long c) {
    unsigned long long d;
    asm("fma.rn.f32x2 %0, %1, %2, %3;" : "=l"(d) : "l"(a), "l"(b), "l"(c));
    return d;
}
__device__ __forceinline__ float sigf(float x) { return 1.0f / (1.0f + expf(-x)); }

// ---------------- init ----------------
__global__ void init_kernel(const float* __restrict__ hidden) {
    int i = blockIdx.x * 256 + threadIdx.x;
    if (i < Bz * Dd) g_h[i] = hidden[i];
}
__global__ void bit_kernel(const int* __restrict__ ids) {
    int b = blockIdx.x, t = threadIdx.x;
    int id = ids[b * Xx + t];
    atomicOr(&g_bit[b * BW + (id >> 5)], 1u << (id & 31));  // idempotent -> deterministic
}

// ---------------- K1: gate GEMMs ----------------
__global__ void k1_kernel(const float* __restrict__ dec,
                          const float* __restrict__ w_ih, const float* __restrict__ w_hh,
                          const float* __restrict__ b_ih, const float* __restrict__ b_hh,
                          int j, int k0) {
    __shared__ float As[32][36];
    __shared__ float Ws[32][33];
    int t = threadIdx.x;
    int lane = t & 31, wr = t >> 5;
    int cbase = blockIdx.x * 32;

    const float* A; int lda; const float* W; const float* bias; float* O;
    if (blockIdx.y == 0) {
        A = k0 ? (dec + (size_t)j * Dd) : g_x;
        lda = k0 ? (Jj * Dd) : Dd;
        W = w_ih; bias = b_ih; O = g_gi;
    } else {
        A = g_h; lda = Dd; W = w_hh; bias = b_hh; O = g_gh;
    }

    int c = lane, bq = wr;
    float acc[4] = {0.f, 0.f, 0.f, 0.f};
    for (int kb = 0; kb < Dd; kb += 32) {
        __syncthreads();
        for (int r = wr; r < 32; r += 8) {
            As[lane][r] = A[(size_t)r * lda + kb + lane];
            Ws[lane][r] = W[(size_t)(cbase + r) * Dd + kb + lane];
        }
        __syncthreads();
        #pragma unroll
        for (int kk = 0; kk < 32; kk++) {
            float w = Ws[kk][c];
            float4 a = *(const float4*)&As[kk][bq * 4];
            acc[0] += a.x * w; acc[1] += a.y * w;
            acc[2] += a.z * w; acc[3] += a.w * w;
        }
    }
    float bb = bias[cbase + c];
    #pragma unroll
    for (int i = 0; i < 4; i++)
        O[(size_t)(bq * 4 + i) * D3 + cbase + c] = acc[i] + bb;
}

// ---------------- K2: h update; attention; context; p_gen ----------------
__global__ void k2_kernel(const float* __restrict__ dec, const float* __restrict__ enc,
                          const int* __restrict__ ids,
                          const float* __restrict__ w_gen, const float* __restrict__ b_gen,
                          int j, int k0) {
    __shared__ float hs[Dd];
    __shared__ float sc[Xx];
    __shared__ float red[256];
    int b = blockIdx.x, t = threadIdx.x;
    const float* gi = g_gi + (size_t)b * D3;
    const float* gh = g_gh + (size_t)b * D3;

    for (int d = t; d < Dd; d += 256) {
        float r = sigf(gi[d] + gh[d]);
        float z = sigf(gi[Dd + d] + gh[Dd + d]);
        float n = tanhf(gi[2 * Dd + d] + r * gh[2 * Dd + d]);
        float h = (1.f - z) * n + z * g_h[(size_t)b * Dd + d];
        hs[d] = h;
        g_h[(size_t)b * Dd + d] = h;
    }
    __syncthreads();

    int lane = t & 31, wr = t >> 5;
    for (int xi = wr; xi < Xx; xi += 8) {
        const float* er = enc + ((size_t)b * Xx + xi) * Dd;
        float s = 0.f;
        for (int kk = lane; kk < Dd; kk += 32) s += er[kk] * hs[kk];
        #pragma unroll
        for (int o = 16; o; o >>= 1) s += __shfl_xor_sync(0xffffffffu, s, o);
        if (lane == 0) sc[xi] = (ids[b * Xx + xi] == 0) ? -1e9f : s;
    }
    __syncthreads();

    red[t] = sc[t]; __syncthreads();
    for (int s2 = 128; s2; s2 >>= 1) { if (t < s2) red[t] = fmaxf(red[t], red[t + s2]); __syncthreads(); }
    float m = red[0]; __syncthreads();
    float ev = expf(sc[t] - m);
    red[t] = ev; __syncthreads();
    for (int s2 = 128; s2; s2 >>= 1) { if (t < s2) red[t] += red[t + s2]; __syncthreads(); }
    float inv = 1.f / red[0];
    __syncthreads();
    float at = ev * inv;
    sc[t] = at;
    g_attn[b * Xx + t] = at;
    __syncthreads();

    const float* xr = k0 ? (dec + ((size_t)b * Jj + j) * Dd) : (g_x + (size_t)b * Dd);
    float pg = 0.f;
    for (int d = t; d < Dd; d += 256) {
        const float* eb = enc + (size_t)b * Xx * Dd + d;
        float c0 = 0.f, c1 = 0.f, c2 = 0.f, c3 = 0.f;
        #pragma unroll 2
        for (int x2 = 0; x2 < Xx; x2 += 4) {
            c0 += sc[x2 + 0] * eb[(size_t)(x2 + 0) * Dd];
            c1 += sc[x2 + 1] * eb[(size_t)(x2 + 1) * Dd];
            c2 += sc[x2 + 2] * eb[(size_t)(x2 + 2) * Dd];
            c3 += sc[x2 + 3] * eb[(size_t)(x2 + 3) * Dd];
        }
        float cx = (c0 + c1) + (c2 + c3);
        pg += w_gen[2 * Dd + d] * cx + w_gen[d] * hs[d] + w_gen[Dd + d] * xr[d];
    }
    red[t] = pg; __syncthreads();
    for (int s2 = 128; s2; s2 >>= 1) { if (t < s2) red[t] += red[t + s2]; __syncthreads(); }
    if (t == 0) g_pgen[b] = sigf(red[0] + b_gen[0]);
}

// ---------------- K3: e = exp(h @ emb^T); fused row-sum + argmax partials ----------
// grid 120, block 256, dynamic smem 82944B. Tile 256v x 32b, thread 4v x 8b.
// e kept v-pair-packed in smem (direct LDS.128 -> FFMA2 operand); h pre-duplicated
// (h,h) pairs; XOR swizzle (quad ^ ((k>>2)&7)) makes the transpose STS conflict-free.
__global__ void k3_kernel(const float* __restrict__ emb) {
    extern __shared__ __align__(16) float sm[];
    float* Eb[2] = { sm, sm + 8192 };                 // 32k x 256v words each
    float* Hb[2] = { sm + 16384, sm + 16384 + 2176 }; // 32k x 68 words each
    __shared__ float sSum[8][8];
    __shared__ unsigned long long sKey[8][8];

    int t = threadIdx.x;
    int blk = blockIdx.x;
    int vbase = blk << 8;
    int vgrp = t & 63, bgrp = t >> 6;
    int b0 = bgrp << 3;
    int v0 = vbase + (vgrp << 2);

    // loader coords
    int r0 = t >> 3, kq = (t & 7) << 2, sw = t & 7;   // sw = ((kq+j)>>2)&7 for j<4
    int rq = (r0 >> 2), rm = r0 & 3;
    int hk = t & 31, hb = t >> 5;

    unsigned long long acc[2][8];
    #pragma unroll
    for (int p = 0; p < 2; p++)
        #pragma unroll
        for (int i = 0; i < 8; i++) acc[p][i] = 0ull;

    // ---- load tile 0 ----
    {
        #pragma unroll
        for (int i = 0; i < 8; i++) {
            int r = r0 + (i << 5);
            int v = vbase + r;
            float4 q = make_float4(0.f, 0.f, 0.f, 0.f);
            if (v < VV) q = *(const float4*)(emb + (size_t)v * Dd + kq);
            int qa = ((rq + (i << 3)) ^ sw) << 2;
            float* p0 = Eb[0] + qa + rm;
            p0[(kq + 0) << 8] = q.x;
            p0[(kq + 1) << 8] = q.y;
            p0[(kq + 2) << 8] = q.z;
            p0[(kq + 3) << 8] = q.w;
        }
        #pragma unroll
        for (int i = 0; i < 4; i++) {
            int b = hb + (i << 3);
            float h = g_h[(size_t)b * Dd + hk];
            *(float2*)(Hb[0] + hk * 68 + (b << 1)) = make_float2(h, h);
        }
    }
    __syncthreads();

    for (int tile = 0; tile < 24; tile++) {
        const float* Ec = Eb[tile & 1];
        const float* Hc = Hb[tile & 1];
        float* En = Eb[(tile + 1) & 1];
        float* Hn = Hb[(tile + 1) & 1];
        bool more = (tile + 1) < 24;

        // prefetch next tile into registers (overlaps with compute)
        float4 pr[8];
        float2 ph[4];
        if (more) {
            int kn = (tile + 1) << 5;
            #pragma unroll
            for (int i = 0; i < 8; i++) {
                int r = r0 + (i << 5);
                int v = vbase + r;
                pr[i] = make_float4(0.f, 0.f, 0.f, 0.f);
                if (v < VV) pr[i] = *(const float4*)(emb + (size_t)v * Dd + kn + kq);
            }
            #pragma unroll
            for (int i = 0; i < 4; i++) {
                int b = hb + (i << 3);
                float h = g_h[(size_t)b * Dd + kn + hk];
                ph[i] = make_float2(h, h);
            }
        }

        // compute 32 k-steps
        #pragma unroll
        for (int kk = 0; kk < 32; kk++) {
            int s = (kk >> 2) & 7;
            ulonglong2 ep = *(const ulonglong2*)(Ec + (kk << 8) + ((vgrp ^ s) << 2));
            #pragma unroll
            for (int i = 0; i < 4; i++) {
                ulonglong2 hp = *(const ulonglong2*)(Hc + kk * 68 + (b0 << 1) + (i << 2));
                acc[0][2 * i]     = fma2(ep.x, hp.x, acc[0][2 * i]);
                acc[1][2 * i]     = fma2(ep.y, hp.x, acc[1][2 * i]);
                acc[0][2 * i + 1] = fma2(ep.x, hp.y, acc[0][2 * i + 1]);
                acc[1][2 * i + 1] = fma2(ep.y, hp.y, acc[1][2 * i + 1]);
            }
        }

        if (more) {
            #pragma unroll
            for (int i = 0; i < 8; i++) {
                int qa = ((rq + (i << 3)) ^ sw) << 2;
                float* p0 = En + qa + rm;
                p0[(kq + 0) << 8] = pr[i].x;
                p0[(kq + 1) << 8] = pr[i].y;
                p0[(kq + 2) << 8] = pr[i].z;
                p0[(kq + 3) << 8] = pr[i].w;
            }
            #pragma unroll
            for (int i = 0; i < 4; i++)
                *(float2*)(Hn + hk * 68 + ((hb + (i << 3)) << 1)) = ph[i];
        }
        __syncthreads();
    }

    // ---- epilogue: exp, store e, per-b partial sum + argmax key ----
    int w = t >> 5, lane = t & 31;
    float lsum[8];
    unsigned long long lkey[8];
    #pragma unroll
    for (int i = 0; i < 8; i++) {
        float x0, x1, x2, x3;
        upk2(acc[0][i], x0, x1);
        upk2(acc[1][i], x2, x3);
        float e0 = (v0 + 0 < VV) ? __expf(x0) : 0.f;
        float e1 = (v0 + 1 < VV) ? __expf(x1) : 0.f;
        float e2 = (v0 + 2 < VV) ? __expf(x2) : 0.f;
        float e3 = (v0 + 3 < VV) ? __expf(x3) : 0.f;
        *(float4*)(g_e + (size_t)(b0 + i) * VP + v0) = make_float4(e0, e1, e2, e3);
        lsum[i] = (e0 + e1) + (e2 + e3);
        unsigned long long k0 = ((unsigned long long)__float_as_uint(e0) << 32) | (unsigned)(~(v0 + 0));
        unsigned long long k1 = ((unsigned long long)__float_as_uint(e1) << 32) | (unsigned)(~(v0 + 1));
        unsigned long long k2 = ((unsigned long long)__float_as_uint(e2) << 32) | (unsigned)(~(v0 + 2));
        unsigned long long k3 = ((unsigned long long)__float_as_uint(e3) << 32) | (unsigned)(~(v0 + 3));
        unsigned long long km = k0 > k1 ? k0 : k1;
        if (k2 > km) km = k2;
        if (k3 > km) km = k3;
        lkey[i] = km;
    }
    #pragma unroll
    for (int i = 0; i < 8; i++) {
        float s = lsum[i];
        unsigned long long k = lkey[i];
        #pragma unroll
        for (int o = 16; o; o >>= 1) {
            s += __shfl_xor_sync(0xffffffffu, s, o);
            unsigned long long ks = __shfl_xor_sync(0xffffffffu, k, o);
            if (ks > k) k = ks;
        }
        if (lane == 0) { sSum[w][i] = s; sKey[w][i] = k; }
    }
    __syncthreads();
    if (t < 32) {
        int bg = t >> 3, i = t & 7;
        float s = sSum[2 * bg][i] + sSum[2 * bg + 1][i];
        unsigned long long ka = sKey[2 * bg][i], kb2 = sKey[2 * bg + 1][i];
        unsigned long long k = ka > kb2 ? ka : kb2;
        int b = (bg << 3) + i;
        g_psum[b * NB + blk] = s;
        g_pkey[b * NB + blk] = k;
    }
}

// ---------------- K4: reduce partials; scatter writes; final argmax; x_next --------
// grid 32, block 256.
__global__ void k4_kernel(const float* __restrict__ emb, const int* __restrict__ ids,
                          float* __restrict__ out, int j, int kstep) {
    __shared__ float rf[256];
    __shared__ unsigned long long rk[256];
    __shared__ float s_at[Xx];
    __shared__ int s_ids[Xx];
    __shared__ int s_am;
    int b = blockIdx.x, t = threadIdx.x;

    rf[t] = (t < NB) ? g_psum[b * NB + t] : 0.f;
    rk[t] = (t < NB) ? g_pkey[b * NB + t] : 0ull;
    s_ids[t] = ids[b * Xx + t];
    s_at[t] = g_attn[b * Xx + t];
    __syncthreads();
    for (int s2 = 128; s2; s2 >>= 1) {
        if (t < s2) {
            rf[t] += rf[t + s2];
            if (rk[t + s2] > rk[t]) rk[t] = rk[t + s2];
        }
        __syncthreads();
    }
    float inv = 1.f / rf[0];
    float pg = g_pgen[b];
    int vd = ~(unsigned)(rk[0] & 0xffffffffu);
    if (t == 0) g_inv[b] = inv;
    __syncthreads();

    const float* erow = g_e + (size_t)b * VP;
    float* orow = out + (((size_t)b * Jj + j) * Kk + kstep) * VV;
    float one_m = 1.f - pg;

    float dval = pg * erow[vd] * inv;
    unsigned long long best =
        ((unsigned long long)__float_as_uint(dval) << 32) | (unsigned)(~vd);
    {
        int v = s_ids[t];
        float a = 0.f;
        #pragma unroll 4
        for (int x2 = 0; x2 < Xx; x2++) a += (s_ids[x2] == v) ? s_at[x2] : 0.f;
        float full = pg * erow[v] * inv + one_m * a;
        orow[v] = full;  // duplicate ids write identical values -> deterministic
        unsigned long long key =
            ((unsigned long long)__float_as_uint(full) << 32) | (unsigned)(~v);
        if (key > best) best = key;
    }
    rk[t] = best; __syncthreads();
    for (int s2 = 128; s2; s2 >>= 1) {
        if (t < s2 && rk[t + s2] > rk[t]) rk[t] = rk[t + s2];
        __syncthreads();
    }
    if (t == 0) s_am = ~(unsigned)(rk[0] & 0xffffffffu);
    __syncthreads();
    int am = s_am;
    for (int d = t; d < Dd; d += 256)
        g_x[(size_t)b * Dd + d] = emb[(size_t)am * Dd + d];
}

// ---------------- K5w: dense output write, skipping id positions ----------------
// grid (30, 32), block 256; 4 v per thread.
// NOTE: out row base = step*30522 floats, 30522 % 4 == 2 -> only 8B-aligned on odd
// steps. Stores must be float2 (8B), never float4.
__global__ void k5w_kernel(float* __restrict__ out, int j, int kstep) {
    int b = blockIdx.y, t = threadIdx.x;
    int v0 = blockIdx.x * 1024 + t * 4;
    if (v0 >= VV) return;
    float pg = g_pgen[b];
    float inv = g_inv[b];
    float sc = pg * inv;
    const float* erow = g_e + (size_t)b * VP;
    float* orow = out + (((size_t)b * Jj + j) * Kk + kstep) * VV;
    unsigned m = (g_bit[b * BW + (v0 >> 5)] >> (v0 & 31)) & 0xFu;
    if (v0 + 3 < VV) {
        float4 e4 = *(const float4*)(erow + v0);
        float o0 = sc * e4.x, o1 = sc * e4.y, o2 = sc * e4.z, o3 = sc * e4.w;
        if (m == 0u) {
            *(float2*)(orow + v0)     = make_float2(o0, o1);
            *(float2*)(orow + v0 + 2) = make_float2(o2, o3);
        } else {
            if (!(m & 1u)) orow[v0 + 0] = o0;
            if (!(m & 2u)) orow[v0 + 1] = o1;
            if (!(m & 4u)) orow[v0 + 2] = o2;
            if (!(m & 8u)) orow[v0 + 3] = o3;
        }
    } else {
        for (int v = v0; v < VV; v++)
            if (!((m >> (v - v0)) & 1u)) orow[v] = sc * erow[v];
    }
}

extern "C" void kernel_launch(void* const* d_in, const int* in_sizes, int n_in,
                              void* d_out, int out_size) {
    const float* dec    = (const float*)d_in[0];
    const float* hidden = (const float*)d_in[1];
    const float* enc    = (const float*)d_in[2];
    const int*   ids    = (const int*)  d_in[3];
    int ei = (in_sizes[4] <= 16) ? 5 : 4;   // skip max_len scalar if present
    const float* emb   = (const float*)d_in[ei + 0];
    const float* w_ih  = (const float*)d_in[ei + 1];
    const float* w_hh  = (const float*)d_in[ei + 2];
    const float* b_ih  = (const float*)d_in[ei + 3];
    const float* b_hh  = (const float*)d_in[ei + 4];
    const float* w_gen = (const float*)d_in[ei + 5];
    const float* b_gen = (const float*)d_in[ei + 6];
    float* out = (float*)d_out;

    const int SMEM3 = (8192 * 2 + 2176 * 2) * 4;  // 82944 bytes
    cudaFuncSetAttribute(k3_kernel, cudaFuncAttributeMaxDynamicSharedMemorySize, SMEM3);

    init_kernel<<<(Bz * Dd + 255) / 256, 256>>>(hidden);
    bit_kernel<<<Bz, Xx>>>(ids);
    for (int j = 0; j < Jj; j++) {
        for (int k = 0; k < Kk; k++) {
            int k0 = (k == 0);
            k1_kernel<<<dim3(72, 2), 256>>>(dec, w_ih, w_hh, b_ih, b_hh, j, k0);
            k2_kernel<<<Bz, 256>>>(dec, enc, ids, w_gen, b_gen, j, k0);
            k3_kernel<<<NB, 256, SMEM3>>>(emb);
            k4_kernel<<<Bz, 256>>>(emb, ids, out, j, k);
            k5w_kernel<<<dim3(30, Bz), 256>>>(out, j, k);
        }
    }
}

// round 5
// speedup vs baseline: 2.3418x; 1.4533x over previous
#include <cuda_runtime.h>
#include <math.h>

#define Bz 32
#define Dd 768
#define D3 2304
#define Xx 256
#define VV 30522
#define VP 30720          // 120*256 padded vocab
#define NB 120            // K3 grid (v-blocks of 256)
#define BW 960            // bitmap words per batch row (30720/32)
#define Jj 4
#define Kk 8

// ---------------- persistent device scratch ----------------
__device__ float g_h[Bz * Dd];
__device__ float g_x[Bz * Dd];
__device__ float g_ctx[Bz * Dd];
__device__ float g_gi[Bz * D3];
__device__ float g_gh[Bz * D3];
__device__ float g_attn[Bz * Xx];
__device__ float g_pgen[Bz];
__device__ float g_inv[Bz];
__device__ __align__(16) float g_e[Bz * VP];
__device__ float g_psum[Bz * NB];
__device__ unsigned long long g_pkey[Bz * NB];
__device__ unsigned int g_bit[Bz * BW];   // id-position bitmap (set-only, idempotent)

// ---------------- packed f32x2 helpers ----------------
__device__ __forceinline__ void upk2(unsigned long long v, float& x, float& y) {
    asm("mov.b64 {%0, %1}, %2;" : "=f"(x), "=f"(y) : "l"(v));
}
__device__ __forceinline__ unsigned long long fma2(unsigned long long a,
                                                   unsigned long long b,
                                                   unsigned long long c) {
    unsigned long long d;
    asm("fma.rn.f32x2 %0, %1, %2, %3;" : "=l"(d) : "l"(a), "l"(b), "l"(c));
    return d;
}
__device__ __forceinline__ float sigf(float x) { return 1.0f / (1.0f + expf(-x)); }

// ---------------- init ----------------
__global__ void init_kernel(const float* __restrict__ hidden) {
    int i = blockIdx.x * 256 + threadIdx.x;
    if (i < Bz * Dd) g_h[i] = hidden[i];
}
__global__ void bit_kernel(const int* __restrict__ ids) {
    int b = blockIdx.x, t = threadIdx.x;
    int id = ids[b * Xx + t];
    atomicOr(&g_bit[b * BW + (id >> 5)], 1u << (id & 31));  // idempotent -> deterministic
}

// ---------------- K1: gate GEMMs ----------------
__global__ void k1_kernel(const float* __restrict__ dec,
                          const float* __restrict__ w_ih, const float* __restrict__ w_hh,
                          const float* __restrict__ b_ih, const float* __restrict__ b_hh,
                          int j, int k0) {
    __shared__ float As[32][36];
    __shared__ float Ws[32][33];
    int t = threadIdx.x;
    int lane = t & 31, wr = t >> 5;
    int cbase = blockIdx.x * 32;

    const float* A; int lda; const float* W; const float* bias; float* O;
    if (blockIdx.y == 0) {
        A = k0 ? (dec + (size_t)j * Dd) : g_x;
        lda = k0 ? (Jj * Dd) : Dd;
        W = w_ih; bias = b_ih; O = g_gi;
    } else {
        A = g_h; lda = Dd; W = w_hh; bias = b_hh; O = g_gh;
    }

    int c = lane, bq = wr;
    float acc[4] = {0.f, 0.f, 0.f, 0.f};
    for (int kb = 0; kb < Dd; kb += 32) {
        __syncthreads();
        for (int r = wr; r < 32; r += 8) {
            As[lane][r] = A[(size_t)r * lda + kb + lane];
            Ws[lane][r] = W[(size_t)(cbase + r) * Dd + kb + lane];
        }
        __syncthreads();
        #pragma unroll
        for (int kk = 0; kk < 32; kk++) {
            float w = Ws[kk][c];
            float4 a = *(const float4*)&As[kk][bq * 4];
            acc[0] += a.x * w; acc[1] += a.y * w;
            acc[2] += a.z * w; acc[3] += a.w * w;
        }
    }
    float bb = bias[cbase + c];
    #pragma unroll
    for (int i = 0; i < 4; i++)
        O[(size_t)(bq * 4 + i) * D3 + cbase + c] = acc[i] + bb;
}

// ---------------- K2a: elementwise GRU h-update ----------------
// grid 96, block 256.
__global__ void k2a_kernel() {
    int i = blockIdx.x * 256 + threadIdx.x;   // i = b*Dd + d
    int b = i / Dd, d = i - b * Dd;
    const float* gi = g_gi + (size_t)b * D3;
    const float* gh = g_gh + (size_t)b * D3;
    float r = sigf(gi[d] + gh[d]);
    float z = sigf(gi[Dd + d] + gh[Dd + d]);
    float n = tanhf(gi[2 * Dd + d] + r * gh[2 * Dd + d]);
    g_h[i] = (1.f - z) * n + z * g_h[i];
}

// ---------------- K2b: attention scores (masked, raw) ----------------
// grid (8, 32), block 256 = 8 warps; each warp does 4 x-positions.
__global__ void k2b_kernel(const float* __restrict__ enc, const int* __restrict__ ids) {
    __shared__ float hs[Dd];
    int b = blockIdx.y, xc = blockIdx.x;
    int t = threadIdx.x, lane = t & 31, w = t >> 5;
    for (int d = t; d < Dd; d += 256) hs[d] = g_h[(size_t)b * Dd + d];
    __syncthreads();
    #pragma unroll
    for (int i = 0; i < 4; i++) {
        int xi = xc * 32 + w * 4 + i;
        const float* er = enc + ((size_t)b * Xx + xi) * Dd;
        float s = 0.f;
        #pragma unroll
        for (int kk = 0; kk < 6; kk++) {
            float4 e4 = *(const float4*)(er + kk * 128 + lane * 4);
            float4 h4 = *(const float4*)(hs + kk * 128 + lane * 4);
            s += e4.x * h4.x + e4.y * h4.y + e4.z * h4.z + e4.w * h4.w;
        }
        #pragma unroll
        for (int o = 16; o; o >>= 1) s += __shfl_xor_sync(0xffffffffu, s, o);
        if (lane == 0)
            g_attn[b * Xx + xi] = (ids[b * Xx + xi] == 0) ? -1e9f : s;
    }
}

// ---------------- K2c: softmax over x, in place ----------------
// grid 32, block 256.
__global__ void k2c_kernel() {
    __shared__ float red[256];
    int b = blockIdx.x, t = threadIdx.x;
    float v = g_attn[b * Xx + t];
    red[t] = v; __syncthreads();
    for (int s2 = 128; s2; s2 >>= 1) { if (t < s2) red[t] = fmaxf(red[t], red[t + s2]); __syncthreads(); }
    float m = red[0]; __syncthreads();
    float ev = expf(v - m);
    red[t] = ev; __syncthreads();
    for (int s2 = 128; s2; s2 >>= 1) { if (t < s2) red[t] += red[t + s2]; __syncthreads(); }
    g_attn[b * Xx + t] = ev / red[0];
}

// ---------------- K2d: context = attn @ enc ----------------
// grid (6, 32), block 128; block owns 128 d-columns.
__global__ void k2d_kernel(const float* __restrict__ enc) {
    __shared__ float s_at[Xx];
    int b = blockIdx.y, t = threadIdx.x;
    int d0 = blockIdx.x * 128;
    s_at[t] = g_attn[b * Xx + t];
    s_at[t + 128] = g_attn[b * Xx + t + 128];
    __syncthreads();
    const float* eb = enc + (size_t)b * Xx * Dd + d0 + t;
    float a0 = 0.f, a1 = 0.f, a2 = 0.f, a3 = 0.f;
    #pragma unroll 2
    for (int x = 0; x < Xx; x += 4) {
        a0 += s_at[x + 0] * eb[(size_t)(x + 0) * Dd];
        a1 += s_at[x + 1] * eb[(size_t)(x + 1) * Dd];
        a2 += s_at[x + 2] * eb[(size_t)(x + 2) * Dd];
        a3 += s_at[x + 3] * eb[(size_t)(x + 3) * Dd];
    }
    g_ctx[(size_t)b * Dd + d0 + t] = (a0 + a1) + (a2 + a3);
}

// ---------------- K3: e = exp(h @ emb^T); fused row-sum + argmax partials ----------
// grid 120, block 256, dynamic smem 82944B. Tile 256v x 32b, thread 4v x 8b.
__global__ void k3_kernel(const float* __restrict__ emb) {
    extern __shared__ __align__(16) float sm[];
    float* Eb[2] = { sm, sm + 8192 };                 // 32k x 256v words each
    float* Hb[2] = { sm + 16384, sm + 16384 + 2176 }; // 32k x 68 words each
    __shared__ float sSum[8][8];
    __shared__ unsigned long long sKey[8][8];

    int t = threadIdx.x;
    int blk = blockIdx.x;
    int vbase = blk << 8;
    int vgrp = t & 63, bgrp = t >> 6;
    int b0 = bgrp << 3;
    int v0 = vbase + (vgrp << 2);

    int r0 = t >> 3, kq = (t & 7) << 2, sw = t & 7;
    int rq = (r0 >> 2), rm = r0 & 3;
    int hk = t & 31, hb = t >> 5;

    unsigned long long acc[2][8];
    #pragma unroll
    for (int p = 0; p < 2; p++)
        #pragma unroll
        for (int i = 0; i < 8; i++) acc[p][i] = 0ull;

    {
        #pragma unroll
        for (int i = 0; i < 8; i++) {
            int r = r0 + (i << 5);
            int v = vbase + r;
            float4 q = make_float4(0.f, 0.f, 0.f, 0.f);
            if (v < VV) q = *(const float4*)(emb + (size_t)v * Dd + kq);
            int qa = ((rq + (i << 3)) ^ sw) << 2;
            float* p0 = Eb[0] + qa + rm;
            p0[(kq + 0) << 8] = q.x;
            p0[(kq + 1) << 8] = q.y;
            p0[(kq + 2) << 8] = q.z;
            p0[(kq + 3) << 8] = q.w;
        }
        #pragma unroll
        for (int i = 0; i < 4; i++) {
            int b = hb + (i << 3);
            float h = g_h[(size_t)b * Dd + hk];
            *(float2*)(Hb[0] + hk * 68 + (b << 1)) = make_float2(h, h);
        }
    }
    __syncthreads();

    for (int tile = 0; tile < 24; tile++) {
        const float* Ec = Eb[tile & 1];
        const float* Hc = Hb[tile & 1];
        float* En = Eb[(tile + 1) & 1];
        float* Hn = Hb[(tile + 1) & 1];
        bool more = (tile + 1) < 24;

        float4 pr[8];
        float2 ph[4];
        if (more) {
            int kn = (tile + 1) << 5;
            #pragma unroll
            for (int i = 0; i < 8; i++) {
                int r = r0 + (i << 5);
                int v = vbase + r;
                pr[i] = make_float4(0.f, 0.f, 0.f, 0.f);
                if (v < VV) pr[i] = *(const float4*)(emb + (size_t)v * Dd + kn + kq);
            }
            #pragma unroll
            for (int i = 0; i < 4; i++) {
                int b = hb + (i << 3);
                float h = g_h[(size_t)b * Dd + kn + hk];
                ph[i] = make_float2(h, h);
            }
        }

        #pragma unroll
        for (int kk = 0; kk < 32; kk++) {
            int s = (kk >> 2) & 7;
            ulonglong2 ep = *(const ulonglong2*)(Ec + (kk << 8) + ((vgrp ^ s) << 2));
            #pragma unroll
            for (int i = 0; i < 4; i++) {
                ulonglong2 hp = *(const ulonglong2*)(Hc + kk * 68 + (b0 << 1) + (i << 2));
                acc[0][2 * i]     = fma2(ep.x, hp.x, acc[0][2 * i]);
                acc[1][2 * i]     = fma2(ep.y, hp.x, acc[1][2 * i]);
                acc[0][2 * i + 1] = fma2(ep.x, hp.y, acc[0][2 * i + 1]);
                acc[1][2 * i + 1] = fma2(ep.y, hp.y, acc[1][2 * i + 1]);
            }
        }

        if (more) {
            #pragma unroll
            for (int i = 0; i < 8; i++) {
                int qa = ((rq + (i << 3)) ^ sw) << 2;
                float* p0 = En + qa + rm;
                p0[(kq + 0) << 8] = pr[i].x;
                p0[(kq + 1) << 8] = pr[i].y;
                p0[(kq + 2) << 8] = pr[i].z;
                p0[(kq + 3) << 8] = pr[i].w;
            }
            #pragma unroll
            for (int i = 0; i < 4; i++)
                *(float2*)(Hn + hk * 68 + ((hb + (i << 3)) << 1)) = ph[i];
        }
        __syncthreads();
    }

    int w = t >> 5, lane = t & 31;
    float lsum[8];
    unsigned long long lkey[8];
    #pragma unroll
    for (int i = 0; i < 8; i++) {
        float x0, x1, x2, x3;
        upk2(acc[0][i], x0, x1);
        upk2(acc[1][i], x2, x3);
        float e0 = (v0 + 0 < VV) ? __expf(x0) : 0.f;
        float e1 = (v0 + 1 < VV) ? __expf(x1) : 0.f;
        float e2 = (v0 + 2 < VV) ? __expf(x2) : 0.f;
        float e3 = (v0 + 3 < VV) ? __expf(x3) : 0.f;
        *(float4*)(g_e + (size_t)(b0 + i) * VP + v0) = make_float4(e0, e1, e2, e3);
        lsum[i] = (e0 + e1) + (e2 + e3);
        unsigned long long k0 = ((unsigned long long)__float_as_uint(e0) << 32) | (unsigned)(~(v0 + 0));
        unsigned long long k1 = ((unsigned long long)__float_as_uint(e1) << 32) | (unsigned)(~(v0 + 1));
        unsigned long long k2 = ((unsigned long long)__float_as_uint(e2) << 32) | (unsigned)(~(v0 + 2));
        unsigned long long k3 = ((unsigned long long)__float_as_uint(e3) << 32) | (unsigned)(~(v0 + 3));
        unsigned long long km = k0 > k1 ? k0 : k1;
        if (k2 > km) km = k2;
        if (k3 > km) km = k3;
        lkey[i] = km;
    }
    #pragma unroll
    for (int i = 0; i < 8; i++) {
        float s = lsum[i];
        unsigned long long k = lkey[i];
        #pragma unroll
        for (int o = 16; o; o >>= 1) {
            s += __shfl_xor_sync(0xffffffffu, s, o);
            unsigned long long ks = __shfl_xor_sync(0xffffffffu, k, o);
            if (ks > k) k = ks;
        }
        if (lane == 0) { sSum[w][i] = s; sKey[w][i] = k; }
    }
    __syncthreads();
    if (t < 32) {
        int bg = t >> 3, i = t & 7;
        float s = sSum[2 * bg][i] + sSum[2 * bg + 1][i];
        unsigned long long ka = sKey[2 * bg][i], kb2 = sKey[2 * bg + 1][i];
        unsigned long long k = ka > kb2 ? ka : kb2;
        int b = (bg << 3) + i;
        g_psum[b * NB + blk] = s;
        g_pkey[b * NB + blk] = k;
    }
}

// ---------------- K4: p_gen; reduce partials; scatter writes; argmax; x_next -------
// grid 32, block 256.
__global__ void k4_kernel(const float* __restrict__ emb, const int* __restrict__ ids,
                          const float* __restrict__ dec,
                          const float* __restrict__ w_gen, const float* __restrict__ b_gen,
                          float* __restrict__ out, int j, int kstep, int k0) {
    __shared__ float rf[256];
    __shared__ unsigned long long rk[256];
    __shared__ float s_at[Xx];
    __shared__ int s_ids[Xx];
    __shared__ int s_am;
    __shared__ float s_pg;
    int b = blockIdx.x, t = threadIdx.x;

    // p_gen dot (uses OLD x; g_x is only overwritten at the very end)
    const float* xr = k0 ? (dec + ((size_t)b * Jj + j) * Dd) : (g_x + (size_t)b * Dd);
    float pgp = 0.f;
    for (int d = t; d < Dd; d += 256)
        pgp += w_gen[d] * g_h[(size_t)b * Dd + d]
             + w_gen[Dd + d] * xr[d]
             + w_gen[2 * Dd + d] * g_ctx[(size_t)b * Dd + d];
    rf[t] = pgp; __syncthreads();
    for (int s2 = 128; s2; s2 >>= 1) { if (t < s2) rf[t] += rf[t + s2]; __syncthreads(); }
    if (t == 0) { s_pg = sigf(rf[0] + b_gen[0]); g_pgen[b] = s_pg; }
    __syncthreads();
    float pg = s_pg;
    __syncthreads();

    rf[t] = (t < NB) ? g_psum[b * NB + t] : 0.f;
    rk[t] = (t < NB) ? g_pkey[b * NB + t] : 0ull;
    s_ids[t] = ids[b * Xx + t];
    s_at[t] = g_attn[b * Xx + t];
    __syncthreads();
    for (int s2 = 128; s2; s2 >>= 1) {
        if (t < s2) {
            rf[t] += rf[t + s2];
            if (rk[t + s2] > rk[t]) rk[t] = rk[t + s2];
        }
        __syncthreads();
    }
    float inv = 1.f / rf[0];
    int vd = ~(unsigned)(rk[0] & 0xffffffffu);
    if (t == 0) g_inv[b] = inv;
    __syncthreads();

    const float* erow = g_e + (size_t)b * VP;
    float* orow = out + (((size_t)b * Jj + j) * Kk + kstep) * VV;
    float one_m = 1.f - pg;

    float dval = pg * erow[vd] * inv;
    unsigned long long best =
        ((unsigned long long)__float_as_uint(dval) << 32) | (unsigned)(~vd);
    {
        int v = s_ids[t];
        float a = 0.f;
        #pragma unroll 4
        for (int x2 = 0; x2 < Xx; x2++) a += (s_ids[x2] == v) ? s_at[x2] : 0.f;
        float full = pg * erow[v] * inv + one_m * a;
        orow[v] = full;  // duplicate ids write identical values -> deterministic
        unsigned long long key =
            ((unsigned long long)__float_as_uint(full) << 32) | (unsigned)(~v);
        if (key > best) best = key;
    }
    rk[t] = best; __syncthreads();
    for (int s2 = 128; s2; s2 >>= 1) {
        if (t < s2 && rk[t + s2] > rk[t]) rk[t] = rk[t + s2];
        __syncthreads();
    }
    if (t == 0) s_am = ~(unsigned)(rk[0] & 0xffffffffu);
    __syncthreads();
    int am = s_am;
    for (int d = t; d < Dd; d += 256)
        g_x[(size_t)b * Dd + d] = emb[(size_t)am * Dd + d];
}

// ---------------- K5w: dense output write, skipping id positions ----------------
// grid (30, 32), block 256; 4 v per thread. float2 stores (row base only 8B-aligned).
__global__ void k5w_kernel(float* __restrict__ out, int j, int kstep) {
    int b = blockIdx.y, t = threadIdx.x;
    int v0 = blockIdx.x * 1024 + t * 4;
    if (v0 >= VV) return;
    float sc = g_pgen[b] * g_inv[b];
    const float* erow = g_e + (size_t)b * VP;
    float* orow = out + (((size_t)b * Jj + j) * Kk + kstep) * VV;
    unsigned m = (g_bit[b * BW + (v0 >> 5)] >> (v0 & 31)) & 0xFu;
    if (v0 + 3 < VV) {
        float4 e4 = *(const float4*)(erow + v0);
        float o0 = sc * e4.x, o1 = sc * e4.y, o2 = sc * e4.z, o3 = sc * e4.w;
        if (m == 0u) {
            *(float2*)(orow + v0)     = make_float2(o0, o1);
            *(float2*)(orow + v0 + 2) = make_float2(o2, o3);
        } else {
            if (!(m & 1u)) orow[v0 + 0] = o0;
            if (!(m & 2u)) orow[v0 + 1] = o1;
            if (!(m & 4u)) orow[v0 + 2] = o2;
            if (!(m & 8u)) orow[v0 + 3] = o3;
        }
    } else {
        for (int v = v0; v < VV; v++)
            if (!((m >> (v - v0)) & 1u)) orow[v] = sc * erow[v];
    }
}

extern "C" void kernel_launch(void* const* d_in, const int* in_sizes, int n_in,
                              void* d_out, int out_size) {
    const float* dec    = (const float*)d_in[0];
    const float* hidden = (const float*)d_in[1];
    const float* enc    = (const float*)d_in[2];
    const int*   ids    = (const int*)  d_in[3];
    int ei = (in_sizes[4] <= 16) ? 5 : 4;   // skip max_len scalar if present
    const float* emb   = (const float*)d_in[ei + 0];
    const float* w_ih  = (const float*)d_in[ei + 1];
    const float* w_hh  = (const float*)d_in[ei + 2];
    const float* b_ih  = (const float*)d_in[ei + 3];
    const float* b_hh  = (const float*)d_in[ei + 4];
    const float* w_gen = (const float*)d_in[ei + 5];
    const float* b_gen = (const float*)d_in[ei + 6];
    float* out = (float*)d_out;

    const int SMEM3 = (8192 * 2 + 2176 * 2) * 4;  // 82944 bytes
    cudaFuncSetAttribute(k3_kernel, cudaFuncAttributeMaxDynamicSharedMemorySize, SMEM3);

    init_kernel<<<(Bz * Dd + 255) / 256, 256>>>(hidden);
    bit_kernel<<<Bz, Xx>>>(ids);
    for (int j = 0; j < Jj; j++) {
        for (int k = 0; k < Kk; k++) {
            int k0 = (k == 0);
            k1_kernel<<<dim3(72, 2), 256>>>(dec, w_ih, w_hh, b_ih, b_hh, j, k0);
            k2a_kernel<<<96, 256>>>();
            k2b_kernel<<<dim3(8, Bz), 256>>>(enc, ids);
            k2c_kernel<<<Bz, 256>>>();
            k2d_kernel<<<dim3(6, Bz), 128>>>(enc);
            k3_kernel<<<NB, 256, SMEM3>>>(emb);
            k4_kernel<<<Bz, 256>>>(emb, ids, dec, w_gen, b_gen, out, j, k, k0);
            k5w_kernel<<<dim3(30, Bz), 256>>>(out, j, k);
        }
    }
}

// round 8
// speedup vs baseline: 3.2668x; 1.3950x over previous
#include <cuda_runtime.h>
#include <cuda_bf16.h>
#include <math.h>

#define Bz 32
#define Dd 768
#define D3 2304
#define Xx 256
#define VV 30522
#define VP 30720          // 240*128 padded vocab
#define NB 240            // K3 grid (v-blocks of 128)
#define BW 960
#define Jj 4
#define Kk 8
#define NCH 24            // K3 k-chunks of 32
// K3 smem element offsets (bf16 elems), rows padded to 40 (80B, conflict-free)
#define SA_H 0
#define SA_L 5120
#define SH_H 10240
#define SH_L 11520
#define SBUF 12800        // elems per buffer (25600 B)

// ---------------- persistent device scratch ----------------
__device__ float g_h[Bz * Dd];
__device__ float g_x[Bz * Dd];
__device__ float g_ctx[Bz * Dd];
__device__ float g_gi[Bz * D3];
__device__ float g_gh[Bz * D3];
__device__ float g_attn[Bz * Xx];
__device__ float g_pgen[Bz];
__device__ float g_inv[Bz];
__device__ __align__(16) float g_e[Bz * VP];
__device__ float g_psum[Bz * NB];
__device__ unsigned long long g_pkey[Bz * NB];
__device__ unsigned int g_bit[Bz * BW];
// split-bf16 emb, row-major [VP][768]
__device__ __align__(16) __nv_bfloat16 g_ebh[(size_t)VP * Dd];
__device__ __align__(16) __nv_bfloat16 g_ebl[(size_t)VP * Dd];
// split-bf16 h, row-major [32][768]
__device__ __align__(16) __nv_bfloat16 g_hhb[Bz * Dd];
__device__ __align__(16) __nv_bfloat16 g_hlb[Bz * Dd];

__device__ __forceinline__ float sigf(float x) { return 1.0f / (1.0f + expf(-x)); }

__device__ __forceinline__ unsigned int s2u(const void* p) {
    unsigned int a;
    asm("{ .reg .u64 t; cvta.to.shared.u64 t, %1; cvt.u32.u64 %0, t; }" : "=r"(a) : "l"(p));
    return a;
}
__device__ __forceinline__ void cpa16(unsigned int d, const void* s) {
    asm volatile("cp.async.cg.shared.global [%0], [%1], 16;" :: "r"(d), "l"(s) : "memory");
}
__device__ __forceinline__ void mma_bf16(float* d, unsigned a0, unsigned a1,
                                         unsigned a2, unsigned a3,
                                         unsigned b0, unsigned b1) {
    asm volatile(
        "mma.sync.aligned.m16n8k16.row.col.f32.bf16.bf16.f32 "
        "{%0,%1,%2,%3}, {%4,%5,%6,%7}, {%8,%9}, {%0,%1,%2,%3};"
        : "+f"(d[0]), "+f"(d[1]), "+f"(d[2]), "+f"(d[3])
        : "r"(a0), "r"(a1), "r"(a2), "r"(a3), "r"(b0), "r"(b1));
}

// ---------------- init ----------------
__global__ void init_kernel(const float* __restrict__ hidden) {
    int i = blockIdx.x * 256 + threadIdx.x;
    if (i < Bz * Dd) g_h[i] = hidden[i];
}
__global__ void bit_kernel(const int* __restrict__ ids) {
    int b = blockIdx.x, t = threadIdx.x;
    int id = ids[b * Xx + t];
    atomicOr(&g_bit[b * BW + (id >> 5)], 1u << (id & 31));
}
// emb -> split bf16 row-major. grid 5760, block 256; 16 elems/thread, no row crossing.
__global__ void k0e_kernel(const float* __restrict__ emb) {
    size_t base = ((size_t)blockIdx.x * 256 + threadIdx.x) * 16;
    int v = (int)(base / Dd);
    bool valid = v < VV;
    const float* src = emb + base;
    #pragma unroll
    for (int i = 0; i < 4; i++) {
        float4 f = valid ? *(const float4*)(src + i * 4) : make_float4(0.f, 0.f, 0.f, 0.f);
        float vs[4] = {f.x, f.y, f.z, f.w};
        #pragma unroll
        for (int u = 0; u < 4; u++) {
            __nv_bfloat16 hi = __float2bfloat16(vs[u]);
            __nv_bfloat16 lo = __float2bfloat16(vs[u] - __bfloat162float(hi));
            g_ebh[base + i * 4 + u] = hi;
            g_ebl[base + i * 4 + u] = lo;
        }
    }
}

// ---------------- K1: gate GEMMs ----------------
__global__ void k1_kernel(const float* __restrict__ dec,
                          const float* __restrict__ w_ih, const float* __restrict__ w_hh,
                          const float* __restrict__ b_ih, const float* __restrict__ b_hh,
                          int j, int k0) {
    __shared__ float As[32][36];
    __shared__ float Ws[32][33];
    int t = threadIdx.x;
    int lane = t & 31, wr = t >> 5;
    int cbase = blockIdx.x * 32;

    const float* A; int lda; const float* W; const float* bias; float* O;
    if (blockIdx.y == 0) {
        A = k0 ? (dec + (size_t)j * Dd) : g_x;
        lda = k0 ? (Jj * Dd) : Dd;
        W = w_ih; bias = b_ih; O = g_gi;
    } else {
        A = g_h; lda = Dd; W = w_hh; bias = b_hh; O = g_gh;
    }

    int c = lane, bq = wr;
    float acc[4] = {0.f, 0.f, 0.f, 0.f};
    for (int kb = 0; kb < Dd; kb += 32) {
        __syncthreads();
        for (int r = wr; r < 32; r += 8) {
            As[lane][r] = A[(size_t)r * lda + kb + lane];
            Ws[lane][r] = W[(size_t)(cbase + r) * Dd + kb + lane];
        }
        __syncthreads();
        #pragma unroll
        for (int kk = 0; kk < 32; kk++) {
            float w = Ws[kk][c];
            float4 a = *(const float4*)&As[kk][bq * 4];
            acc[0] += a.x * w; acc[1] += a.y * w;
            acc[2] += a.z * w; acc[3] += a.w * w;
        }
    }
    float bb = bias[cbase + c];
    #pragma unroll
    for (int i = 0; i < 4; i++)
        O[(size_t)(bq * 4 + i) * D3 + cbase + c] = acc[i] + bb;
}

// ---------------- K2a: elementwise GRU h-update ----------------
__global__ void k2a_kernel() {
    int i = blockIdx.x * 256 + threadIdx.x;
    int b = i / Dd, d = i - b * Dd;
    const float* gi = g_gi + (size_t)b * D3;
    const float* gh = g_gh + (size_t)b * D3;
    float r = sigf(gi[d] + gh[d]);
    float z = sigf(gi[Dd + d] + gh[Dd + d]);
    float n = tanhf(gi[2 * Dd + d] + r * gh[2 * Dd + d]);
    g_h[i] = (1.f - z) * n + z * g_h[i];
}

// ---------------- K2h: h -> split bf16 row-major (per step) ----------------
// grid 96, block 256.
__global__ void k2h_kernel() {
    int i = blockIdx.x * 256 + threadIdx.x;
    float x = g_h[i];
    __nv_bfloat16 hi = __float2bfloat16(x);
    __nv_bfloat16 lo = __float2bfloat16(x - __bfloat162float(hi));
    g_hhb[i] = hi;
    g_hlb[i] = lo;
}

// ---------------- K2b: attention scores ----------------
__global__ void k2b_kernel(const float* __restrict__ enc, const int* __restrict__ ids) {
    __shared__ float hs[Dd];
    int b = blockIdx.y, xc = blockIdx.x;
    int t = threadIdx.x, lane = t & 31, w = t >> 5;
    for (int d = t; d < Dd; d += 256) hs[d] = g_h[(size_t)b * Dd + d];
    __syncthreads();
    #pragma unroll
    for (int i = 0; i < 4; i++) {
        int xi = xc * 32 + w * 4 + i;
        const float* er = enc + ((size_t)b * Xx + xi) * Dd;
        float s = 0.f;
        #pragma unroll
        for (int kk = 0; kk < 6; kk++) {
            float4 e4 = *(const float4*)(er + kk * 128 + lane * 4);
            float4 h4 = *(const float4*)(hs + kk * 128 + lane * 4);
            s += e4.x * h4.x + e4.y * h4.y + e4.z * h4.z + e4.w * h4.w;
        }
        #pragma unroll
        for (int o = 16; o; o >>= 1) s += __shfl_xor_sync(0xffffffffu, s, o);
        if (lane == 0)
            g_attn[b * Xx + xi] = (ids[b * Xx + xi] == 0) ? -1e9f : s;
    }
}

// ---------------- K2c: softmax over x ----------------
__global__ void k2c_kernel() {
    __shared__ float red[256];
    int b = blockIdx.x, t = threadIdx.x;
    float v = g_attn[b * Xx + t];
    red[t] = v; __syncthreads();
    for (int s2 = 128; s2; s2 >>= 1) { if (t < s2) red[t] = fmaxf(red[t], red[t + s2]); __syncthreads(); }
    float m = red[0]; __syncthreads();
    float ev = expf(v - m);
    red[t] = ev; __syncthreads();
    for (int s2 = 128; s2; s2 >>= 1) { if (t < s2) red[t] += red[t + s2]; __syncthreads(); }
    g_attn[b * Xx + t] = ev / red[0];
}

// ---------------- K2d: context = attn @ enc ----------------
__global__ void k2d_kernel(const float* __restrict__ enc) {
    __shared__ float s_at[Xx];
    int b = blockIdx.y, t = threadIdx.x;
    int d0 = blockIdx.x * 128;
    s_at[t] = g_attn[b * Xx + t];
    s_at[t + 128] = g_attn[b * Xx + t + 128];
    __syncthreads();
    const float* eb = enc + (size_t)b * Xx * Dd + d0 + t;
    float a0 = 0.f, a1 = 0.f, a2 = 0.f, a3 = 0.f;
    #pragma unroll 2
    for (int x = 0; x < Xx; x += 4) {
        a0 += s_at[x + 0] * eb[(size_t)(x + 0) * Dd];
        a1 += s_at[x + 1] * eb[(size_t)(x + 1) * Dd];
        a2 += s_at[x + 2] * eb[(size_t)(x + 2) * Dd];
        a3 += s_at[x + 3] * eb[(size_t)(x + 3) * Dd];
    }
    g_ctx[(size_t)b * Dd + d0 + t] = (a0 + a1) + (a2 + a3);
}

// ---------------- K3: HMMA split-bf16 GEMM, e = exp(emb @ h^T) ----------------
// grid 240, block 256 (8 warps), dyn smem 51200B, 2 blocks/SM.
// Per block: D[128v x 32b]; warp w owns v rows [16w,16w+16), 4 n-tiles of 8 b.
__global__ void __launch_bounds__(256, 2) k3_kernel() {
    extern __shared__ __align__(16) __nv_bfloat16 sm[];
    __shared__ float sSum[8][32];
    __shared__ unsigned long long sKey[8][32];
    int t = threadIdx.x, w = t >> 5, lane = t & 31;
    int q = lane & 3, r8 = lane >> 2;
    int blk = blockIdx.x, vbase = blk << 7;
    unsigned int sbase = s2u(sm);

    float acc[4][4];
    #pragma unroll
    for (int nt = 0; nt < 4; nt++)
        #pragma unroll
        for (int i = 0; i < 4; i++) acc[nt][i] = 0.f;

    // loader coords: A rows lr, lr+64 x 8-bf16 col lc; H row hr x col hc
    int lr = t >> 2, lc = (t & 3) * 8;
    int hr = (t & 127) >> 2, hc = ((t & 127) & 3) * 8;
    const __nv_bfloat16* gA0h = g_ebh + (size_t)(vbase + lr) * Dd + lc;
    const __nv_bfloat16* gA1h = g_ebh + (size_t)(vbase + lr + 64) * Dd + lc;
    const __nv_bfloat16* gA0l = g_ebl + (size_t)(vbase + lr) * Dd + lc;
    const __nv_bfloat16* gA1l = g_ebl + (size_t)(vbase + lr + 64) * Dd + lc;
    const __nv_bfloat16* gH = (t < 128 ? g_hhb : g_hlb) + (size_t)hr * Dd + hc;
    unsigned int dA0 = (unsigned)((SA_H + lr * 40 + lc) * 2);
    unsigned int dA1 = (unsigned)((SA_H + (lr + 64) * 40 + lc) * 2);
    unsigned int dL0 = (unsigned)((SA_L + lr * 40 + lc) * 2);
    unsigned int dL1 = (unsigned)((SA_L + (lr + 64) * 40 + lc) * 2);
    unsigned int dH = (unsigned)(((t < 128 ? SH_H : SH_L) + hr * 40 + hc) * 2);

    // prologue: load chunk 0 into buffer 0
    {
        cpa16(sbase + dA0, gA0h);
        cpa16(sbase + dA1, gA1h);
        cpa16(sbase + dL0, gA0l);
        cpa16(sbase + dL1, gA1l);
        cpa16(sbase + dH, gH);
        asm volatile("cp.async.commit_group;" ::: "memory");
        asm volatile("cp.async.wait_group 0;" ::: "memory");
    }
    __syncthreads();

    for (int kc = 0; kc < NCH; kc++) {
        int buf = kc & 1;
        if (kc + 1 < NCH) {
            unsigned int nb = sbase + (buf ^ 1) * (SBUF * 2);
            int ko = (kc + 1) * 32;
            cpa16(nb + dA0, gA0h + ko);
            cpa16(nb + dA1, gA1h + ko);
            cpa16(nb + dL0, gA0l + ko);
            cpa16(nb + dL1, gA1l + ko);
            cpa16(nb + dH, gH + ko);
            asm volatile("cp.async.commit_group;" ::: "memory");
        }
        const __nv_bfloat16* Ah = sm + buf * SBUF + SA_H;
        const __nv_bfloat16* Al = sm + buf * SBUF + SA_L;
        const __nv_bfloat16* Hh = sm + buf * SBUF + SH_H;
        const __nv_bfloat16* Hl = sm + buf * SBUF + SH_L;
        int ar = w * 16 + r8;
        #pragma unroll
        for (int s = 0; s < 2; s++) {
            int k0 = s * 16, ac = k0 + q * 2;
            unsigned ah0 = *(const unsigned*)&Ah[ar * 40 + ac];
            unsigned ah1 = *(const unsigned*)&Ah[(ar + 8) * 40 + ac];
            unsigned ah2 = *(const unsigned*)&Ah[ar * 40 + ac + 8];
            unsigned ah3 = *(const unsigned*)&Ah[(ar + 8) * 40 + ac + 8];
            unsigned al0 = *(const unsigned*)&Al[ar * 40 + ac];
            unsigned al1 = *(const unsigned*)&Al[(ar + 8) * 40 + ac];
            unsigned al2 = *(const unsigned*)&Al[ar * 40 + ac + 8];
            unsigned al3 = *(const unsigned*)&Al[(ar + 8) * 40 + ac + 8];
            #pragma unroll
            for (int nt = 0; nt < 4; nt++) {
                int bn = (nt * 8 + r8) * 40 + k0 + q * 2;
                unsigned bh0 = *(const unsigned*)&Hh[bn];
                unsigned bh1 = *(const unsigned*)&Hh[bn + 8];
                unsigned bl0 = *(const unsigned*)&Hl[bn];
                unsigned bl1 = *(const unsigned*)&Hl[bn + 8];
                mma_bf16(acc[nt], ah0, ah1, ah2, ah3, bh0, bh1);
                mma_bf16(acc[nt], al0, al1, al2, al3, bh0, bh1);
                mma_bf16(acc[nt], ah0, ah1, ah2, ah3, bl0, bl1);
            }
        }
        if (kc + 1 < NCH)
            asm volatile("cp.async.wait_group 0;" ::: "memory");
        __syncthreads();
    }

    // epilogue: exp, store g_e, per-b partial sum + argmax key
    int v0 = vbase + w * 16 + r8, v1 = v0 + 8;
    bool ok0 = v0 < VV, ok1 = v1 < VV;
    #pragma unroll
    for (int nt = 0; nt < 4; nt++) {
        float e00 = ok0 ? __expf(acc[nt][0]) : 0.f;
        float e01 = ok0 ? __expf(acc[nt][1]) : 0.f;
        float e10 = ok1 ? __expf(acc[nt][2]) : 0.f;
        float e11 = ok1 ? __expf(acc[nt][3]) : 0.f;
        int b0 = nt * 8 + q * 2, b1 = b0 + 1;
        g_e[(size_t)b0 * VP + v0] = e00;
        g_e[(size_t)b1 * VP + v0] = e01;
        g_e[(size_t)b0 * VP + v1] = e10;
        g_e[(size_t)b1 * VP + v1] = e11;
        float s0 = e00 + e10, s1 = e01 + e11;
        unsigned long long k00 = ((unsigned long long)__float_as_uint(e00) << 32) | (unsigned)(~v0);
        unsigned long long k10 = ((unsigned long long)__float_as_uint(e10) << 32) | (unsigned)(~v1);
        unsigned long long k01 = ((unsigned long long)__float_as_uint(e01) << 32) | (unsigned)(~v0);
        unsigned long long k11 = ((unsigned long long)__float_as_uint(e11) << 32) | (unsigned)(~v1);
        unsigned long long key0 = k00 > k10 ? k00 : k10;
        unsigned long long key1 = k01 > k11 ? k01 : k11;
        #pragma unroll
        for (int o = 4; o <= 16; o <<= 1) {
            s0 += __shfl_xor_sync(0xffffffffu, s0, o);
            s1 += __shfl_xor_sync(0xffffffffu, s1, o);
            unsigned long long t0 = __shfl_xor_sync(0xffffffffu, key0, o);
            unsigned long long t1 = __shfl_xor_sync(0xffffffffu, key1, o);
            if (t0 > key0) key0 = t0;
            if (t1 > key1) key1 = t1;
        }
        if (r8 == 0) {
            sSum[w][b0] = s0; sSum[w][b1] = s1;
            sKey[w][b0] = key0; sKey[w][b1] = key1;
        }
    }
    __syncthreads();
    if (t < 32) {
        float s = 0.f;
        unsigned long long k = 0ull;
        #pragma unroll
        for (int w2 = 0; w2 < 8; w2++) {
            s += sSum[w2][t];
            if (sKey[w2][t] > k) k = sKey[w2][t];
        }
        g_psum[t * NB + blk] = s;
        g_pkey[t * NB + blk] = k;
    }
}

// ---------------- K4: p_gen; reduce partials; scatter writes; argmax; x_next -------
__global__ void k4_kernel(const float* __restrict__ emb, const int* __restrict__ ids,
                          const float* __restrict__ dec,
                          const float* __restrict__ w_gen, const float* __restrict__ b_gen,
                          float* __restrict__ out, int j, int kstep, int k0) {
    __shared__ float rf[256];
    __shared__ unsigned long long rk[256];
    __shared__ float s_at[Xx];
    __shared__ int s_ids[Xx];
    __shared__ int s_am;
    __shared__ float s_pg;
    int b = blockIdx.x, t = threadIdx.x;

    const float* xr = k0 ? (dec + ((size_t)b * Jj + j) * Dd) : (g_x + (size_t)b * Dd);
    float pgp = 0.f;
    for (int d = t; d < Dd; d += 256)
        pgp += w_gen[d] * g_h[(size_t)b * Dd + d]
             + w_gen[Dd + d] * xr[d]
             + w_gen[2 * Dd + d] * g_ctx[(size_t)b * Dd + d];
    rf[t] = pgp; __syncthreads();
    for (int s2 = 128; s2; s2 >>= 1) { if (t < s2) rf[t] += rf[t + s2]; __syncthreads(); }
    if (t == 0) { s_pg = sigf(rf[0] + b_gen[0]); g_pgen[b] = s_pg; }
    __syncthreads();
    float pg = s_pg;
    __syncthreads();

    rf[t] = (t < NB) ? g_psum[b * NB + t] : 0.f;
    rk[t] = (t < NB) ? g_pkey[b * NB + t] : 0ull;
    s_ids[t] = ids[b * Xx + t];
    s_at[t] = g_attn[b * Xx + t];
    __syncthreads();
    for (int s2 = 128; s2; s2 >>= 1) {
        if (t < s2) {
            rf[t] += rf[t + s2];
            if (rk[t + s2] > rk[t]) rk[t] = rk[t + s2];
        }
        __syncthreads();
    }
    float inv = 1.f / rf[0];
    int vd = ~(unsigned)(rk[0] & 0xffffffffu);
    if (t == 0) g_inv[b] = inv;
    __syncthreads();

    const float* erow = g_e + (size_t)b * VP;
    float* orow = out + (((size_t)b * Jj + j) * Kk + kstep) * VV;
    float one_m = 1.f - pg;

    float dval = pg * erow[vd] * inv;
    unsigned long long best =
        ((unsigned long long)__float_as_uint(dval) << 32) | (unsigned)(~vd);
    {
        int v = s_ids[t];
        float a = 0.f;
        #pragma unroll 4
        for (int x2 = 0; x2 < Xx; x2++) a += (s_ids[x2] == v) ? s_at[x2] : 0.f;
        float full = pg * erow[v] * inv + one_m * a;
        orow[v] = full;
        unsigned long long key =
            ((unsigned long long)__float_as_uint(full) << 32) | (unsigned)(~v);
        if (key > best) best = key;
    }
    rk[t] = best; __syncthreads();
    for (int s2 = 128; s2; s2 >>= 1) {
        if (t < s2 && rk[t + s2] > rk[t]) rk[t] = rk[t + s2];
        __syncthreads();
    }
    if (t == 0) s_am = ~(unsigned)(rk[0] & 0xffffffffu);
    __syncthreads();
    int am = s_am;
    for (int d = t; d < Dd; d += 256)
        g_x[(size_t)b * Dd + d] = emb[(size_t)am * Dd + d];
}

// ---------------- K5w: dense output write ----------------
__global__ void k5w_kernel(float* __restrict__ out, int j, int kstep) {
    int b = blockIdx.y, t = threadIdx.x;
    int v0 = blockIdx.x * 1024 + t * 4;
    if (v0 >= VV) return;
    float sc = g_pgen[b] * g_inv[b];
    const float* erow = g_e + (size_t)b * VP;
    float* orow = out + (((size_t)b * Jj + j) * Kk + kstep) * VV;
    unsigned m = (g_bit[b * BW + (v0 >> 5)] >> (v0 & 31)) & 0xFu;
    if (v0 + 3 < VV) {
        float4 e4 = *(const float4*)(erow + v0);
        float o0 = sc * e4.x, o1 = sc * e4.y, o2 = sc * e4.z, o3 = sc * e4.w;
        if (m == 0u) {
            *(float2*)(orow + v0)     = make_float2(o0, o1);
            *(float2*)(orow + v0 + 2) = make_float2(o2, o3);
        } else {
            if (!(m & 1u)) orow[v0 + 0] = o0;
            if (!(m & 2u)) orow[v0 + 1] = o1;
            if (!(m & 4u)) orow[v0 + 2] = o2;
            if (!(m & 8u)) orow[v0 + 3] = o3;
        }
    } else {
        for (int v = v0; v < VV; v++)
            if (!((m >> (v - v0)) & 1u)) orow[v] = sc * erow[v];
    }
}

extern "C" void kernel_launch(void* const* d_in, const int* in_sizes, int n_in,
                              void* d_out, int out_size) {
    const float* dec    = (const float*)d_in[0];
    const float* hidden = (const float*)d_in[1];
    const float* enc    = (const float*)d_in[2];
    const int*   ids    = (const int*)  d_in[3];
    int ei = (in_sizes[4] <= 16) ? 5 : 4;
    const float* emb   = (const float*)d_in[ei + 0];
    const float* w_ih  = (const float*)d_in[ei + 1];
    const float* w_hh  = (const float*)d_in[ei + 2];
    const float* b_ih  = (const float*)d_in[ei + 3];
    const float* b_hh  = (const float*)d_in[ei + 4];
    const float* w_gen = (const float*)d_in[ei + 5];
    const float* b_gen = (const float*)d_in[ei + 6];
    float* out = (float*)d_out;

    const int SMEM3 = SBUF * 2 * 2;  // 51200 bytes
    cudaFuncSetAttribute(k3_kernel, cudaFuncAttributeMaxDynamicSharedMemorySize, SMEM3);

    init_kernel<<<(Bz * Dd + 255) / 256, 256>>>(hidden);
    bit_kernel<<<Bz, Xx>>>(ids);
    k0e_kernel<<<(int)(((size_t)VP * Dd) / 4096), 256>>>(emb);
    for (int j = 0; j < Jj; j++) {
        for (int k = 0; k < Kk; k++) {
            int k0 = (k == 0);
            k1_kernel<<<dim3(72, 2), 256>>>(dec, w_ih, w_hh, b_ih, b_hh, j, k0);
            k2a_kernel<<<96, 256>>>();
            k2h_kernel<<<96, 256>>>();
            k2b_kernel<<<dim3(8, Bz), 256>>>(enc, ids);
            k2c_kernel<<<Bz, 256>>>();
            k2d_kernel<<<dim3(6, Bz), 128>>>(enc);
            k3_kernel<<<NB, 256, SMEM3>>>();
            k4_kernel<<<Bz, 256>>>(emb, ids, dec, w_gen, b_gen, out, j, k, k0);
            k5w_kernel<<<dim3(30, Bz), 256>>>(out, j, k);
        }
    }
}

// round 10
// speedup vs baseline: 4.6401x; 1.4204x over previous
#include <cuda_runtime.h>
#include <cuda_bf16.h>
#include <math.h>

#define Bz 32
#define Dd 768
#define D3 2304
#define Xx 256
#define VV 30522
#define VP 30720          // 240*128 padded vocab
#define NB 240            // K3 grid (v-blocks of 128)
#define BW 960
#define Jj 4
#define Kk 8
#define NCH 24            // k-chunks of 32
// smem element offsets (bf16 elems), rows padded to 40 (80B, conflict-free)
#define SA_H 0
#define SA_L 5120
#define SH_H 10240
#define SH_L 11520
#define SBUF 12800        // elems per buffer (25600 B)

// ---------------- persistent device scratch ----------------
__device__ float g_h[Bz * Dd];
__device__ float g_x[Bz * Dd];
__device__ float g_ctx[Bz * Dd];
__device__ float g_giT[D3 * Bz];   // transposed gates [c][b]
__device__ float g_ghT[D3 * Bz];
__device__ float g_attn[Bz * Xx];
__device__ float g_pgen[Bz];
__device__ float g_inv[Bz];
__device__ __align__(16) float g_e[Bz * VP];
__device__ float g_psum[Bz * NB];
__device__ unsigned long long g_pkey[Bz * NB];
__device__ unsigned int g_bit[Bz * BW];
// split-bf16 emb [VP][768]
__device__ __align__(16) __nv_bfloat16 g_ebh[(size_t)VP * Dd];
__device__ __align__(16) __nv_bfloat16 g_ebl[(size_t)VP * Dd];
// split-bf16 weights [2304][768]
__device__ __align__(16) __nv_bfloat16 g_wih_h[(size_t)D3 * Dd];
__device__ __align__(16) __nv_bfloat16 g_wih_l[(size_t)D3 * Dd];
__device__ __align__(16) __nv_bfloat16 g_whh_h[(size_t)D3 * Dd];
__device__ __align__(16) __nv_bfloat16 g_whh_l[(size_t)D3 * Dd];
// split-bf16 h and x [32][768]
__device__ __align__(16) __nv_bfloat16 g_hhb[Bz * Dd];
__device__ __align__(16) __nv_bfloat16 g_hlb[Bz * Dd];
__device__ __align__(16) __nv_bfloat16 g_xhb[Bz * Dd];
__device__ __align__(16) __nv_bfloat16 g_xlb[Bz * Dd];

__device__ __forceinline__ float sigf(float x) { return 1.0f / (1.0f + expf(-x)); }

__device__ __forceinline__ unsigned int s2u(const void* p) {
    unsigned int a;
    asm("{ .reg .u64 t; cvta.to.shared.u64 t, %1; cvt.u32.u64 %0, t; }" : "=r"(a) : "l"(p));
    return a;
}
__device__ __forceinline__ void cpa16(unsigned int d, const void* s) {
    asm volatile("cp.async.cg.shared.global [%0], [%1], 16;" :: "r"(d), "l"(s) : "memory");
}
__device__ __forceinline__ void mma_bf16(float* d, unsigned a0, unsigned a1,
                                         unsigned a2, unsigned a3,
                                         unsigned b0, unsigned b1) {
    asm volatile(
        "mma.sync.aligned.m16n8k16.row.col.f32.bf16.bf16.f32 "
        "{%0,%1,%2,%3}, {%4,%5,%6,%7}, {%8,%9}, {%0,%1,%2,%3};"
        : "+f"(d[0]), "+f"(d[1]), "+f"(d[2]), "+f"(d[3])
        : "r"(a0), "r"(a1), "r"(a2), "r"(a3), "r"(b0), "r"(b1));
}

// ---------------- init ----------------
__global__ void init_kernel(const float* __restrict__ hidden) {
    int i = blockIdx.x * 256 + threadIdx.x;
    if (i < Bz * Dd) g_h[i] = hidden[i];
}
__global__ void bit_kernel(const int* __restrict__ ids) {
    int b = blockIdx.x, t = threadIdx.x;
    int id = ids[b * Xx + t];
    atomicOr(&g_bit[b * BW + (id >> 5)], 1u << (id & 31));
}
// emb -> split bf16 row-major. grid 5760, block 256; 16 elems/thread.
__global__ void k0e_kernel(const float* __restrict__ emb) {
    size_t base = ((size_t)blockIdx.x * 256 + threadIdx.x) * 16;
    int v = (int)(base / Dd);
    bool valid = v < VV;
    const float* src = emb + base;
    #pragma unroll
    for (int i = 0; i < 4; i++) {
        float4 f = valid ? *(const float4*)(src + i * 4) : make_float4(0.f, 0.f, 0.f, 0.f);
        float vs[4] = {f.x, f.y, f.z, f.w};
        #pragma unroll
        for (int u = 0; u < 4; u++) {
            __nv_bfloat16 hi = __float2bfloat16(vs[u]);
            __nv_bfloat16 lo = __float2bfloat16(vs[u] - __bfloat162float(hi));
            g_ebh[base + i * 4 + u] = hi;
            g_ebl[base + i * 4 + u] = lo;
        }
    }
}
// weights -> split bf16. grid 1728, block 256, 4 elems/thread. which: 0=ih, 1=hh.
__global__ void k0w_kernel(const float* __restrict__ w, int which) {
    size_t base = ((size_t)blockIdx.x * 256 + threadIdx.x) * 4;
    __nv_bfloat16* oh = which ? g_whh_h : g_wih_h;
    __nv_bfloat16* ol = which ? g_whh_l : g_wih_l;
    float4 f = *(const float4*)(w + base);
    float vs[4] = {f.x, f.y, f.z, f.w};
    #pragma unroll
    for (int u = 0; u < 4; u++) {
        __nv_bfloat16 hi = __float2bfloat16(vs[u]);
        __nv_bfloat16 lo = __float2bfloat16(vs[u] - __bfloat162float(hi));
        oh[base + u] = hi;
        ol[base + u] = lo;
    }
}

// ---------------- K2x: x -> split bf16 (per step) ----------------
__global__ void k2x_kernel(const float* __restrict__ dec, int j, int k0) {
    int i = blockIdx.x * 256 + threadIdx.x;   // i = b*Dd + d
    int b = i / Dd, d = i - b * Dd;
    float x = k0 ? dec[((size_t)b * Jj + j) * Dd + d] : g_x[i];
    __nv_bfloat16 hi = __float2bfloat16(x);
    __nv_bfloat16 lo = __float2bfloat16(x - __bfloat162float(hi));
    g_xhb[i] = hi;
    g_xlb[i] = lo;
}

// ---------------- K1h: HMMA gate GEMMs, giT/ghT = W @ {x,h}^T + bias ----------
// grid (18, 2), block 256, dyn smem 51200B. Per block: 128 c-rows x 32 b.
__global__ void __launch_bounds__(256, 2) k1h_kernel(const float* __restrict__ b_ih,
                                                     const float* __restrict__ b_hh) {
    extern __shared__ __align__(16) __nv_bfloat16 sm[];
    int t = threadIdx.x, w = t >> 5, lane = t & 31;
    int q = lane & 3, r8 = lane >> 2;
    int vbase = blockIdx.x << 7;
    unsigned int sbase = s2u(sm);

    const __nv_bfloat16 *Wh, *Wl, *Bh, *Bl;
    const float* bias;
    float* OT;
    if (blockIdx.y == 0) {
        Wh = g_wih_h; Wl = g_wih_l; Bh = g_xhb; Bl = g_xlb; bias = b_ih; OT = g_giT;
    } else {
        Wh = g_whh_h; Wl = g_whh_l; Bh = g_hhb; Bl = g_hlb; bias = b_hh; OT = g_ghT;
    }

    float acc[4][4];
    #pragma unroll
    for (int nt = 0; nt < 4; nt++)
        #pragma unroll
        for (int i = 0; i < 4; i++) acc[nt][i] = 0.f;

    int lr = t >> 2, lc = (t & 3) * 8;
    int hr = (t & 127) >> 2, hc = ((t & 127) & 3) * 8;
    const __nv_bfloat16* gA0h = Wh + (size_t)(vbase + lr) * Dd + lc;
    const __nv_bfloat16* gA1h = Wh + (size_t)(vbase + lr + 64) * Dd + lc;
    const __nv_bfloat16* gA0l = Wl + (size_t)(vbase + lr) * Dd + lc;
    const __nv_bfloat16* gA1l = Wl + (size_t)(vbase + lr + 64) * Dd + lc;
    const __nv_bfloat16* gH = (t < 128 ? Bh : Bl) + (size_t)hr * Dd + hc;
    unsigned int dA0 = (unsigned)((SA_H + lr * 40 + lc) * 2);
    unsigned int dA1 = (unsigned)((SA_H + (lr + 64) * 40 + lc) * 2);
    unsigned int dL0 = (unsigned)((SA_L + lr * 40 + lc) * 2);
    unsigned int dL1 = (unsigned)((SA_L + (lr + 64) * 40 + lc) * 2);
    unsigned int dH = (unsigned)(((t < 128 ? SH_H : SH_L) + hr * 40 + hc) * 2);

    {
        cpa16(sbase + dA0, gA0h);
        cpa16(sbase + dA1, gA1h);
        cpa16(sbase + dL0, gA0l);
        cpa16(sbase + dL1, gA1l);
        cpa16(sbase + dH, gH);
        asm volatile("cp.async.commit_group;" ::: "memory");
        asm volatile("cp.async.wait_group 0;" ::: "memory");
    }
    __syncthreads();

    for (int kc = 0; kc < NCH; kc++) {
        int buf = kc & 1;
        if (kc + 1 < NCH) {
            unsigned int nb = sbase + (buf ^ 1) * (SBUF * 2);
            int ko = (kc + 1) * 32;
            cpa16(nb + dA0, gA0h + ko);
            cpa16(nb + dA1, gA1h + ko);
            cpa16(nb + dL0, gA0l + ko);
            cpa16(nb + dL1, gA1l + ko);
            cpa16(nb + dH, gH + ko);
            asm volatile("cp.async.commit_group;" ::: "memory");
        }
        const __nv_bfloat16* Ah = sm + buf * SBUF + SA_H;
        const __nv_bfloat16* Al = sm + buf * SBUF + SA_L;
        const __nv_bfloat16* Hh = sm + buf * SBUF + SH_H;
        const __nv_bfloat16* Hl = sm + buf * SBUF + SH_L;
        int ar = w * 16 + r8;
        #pragma unroll
        for (int s = 0; s < 2; s++) {
            int k0 = s * 16, ac = k0 + q * 2;
            unsigned ah0 = *(const unsigned*)&Ah[ar * 40 + ac];
            unsigned ah1 = *(const unsigned*)&Ah[(ar + 8) * 40 + ac];
            unsigned ah2 = *(const unsigned*)&Ah[ar * 40 + ac + 8];
            unsigned ah3 = *(const unsigned*)&Ah[(ar + 8) * 40 + ac + 8];
            unsigned al0 = *(const unsigned*)&Al[ar * 40 + ac];
            unsigned al1 = *(const unsigned*)&Al[(ar + 8) * 40 + ac];
            unsigned al2 = *(const unsigned*)&Al[ar * 40 + ac + 8];
            unsigned al3 = *(const unsigned*)&Al[(ar + 8) * 40 + ac + 8];
            #pragma unroll
            for (int nt = 0; nt < 4; nt++) {
                int bn = (nt * 8 + r8) * 40 + k0 + q * 2;
                unsigned bh0 = *(const unsigned*)&Hh[bn];
                unsigned bh1 = *(const unsigned*)&Hh[bn + 8];
                unsigned bl0 = *(const unsigned*)&Hl[bn];
                unsigned bl1 = *(const unsigned*)&Hl[bn + 8];
                mma_bf16(acc[nt], ah0, ah1, ah2, ah3, bh0, bh1);
                mma_bf16(acc[nt], al0, al1, al2, al3, bh0, bh1);
                mma_bf16(acc[nt], ah0, ah1, ah2, ah3, bl0, bl1);
            }
        }
        if (kc + 1 < NCH)
            asm volatile("cp.async.wait_group 0;" ::: "memory");
        __syncthreads();
    }

    int v0 = vbase + w * 16 + r8, v1 = v0 + 8;
    float bi0 = bias[v0], bi1 = bias[v1];
    #pragma unroll
    for (int nt = 0; nt < 4; nt++) {
        int b0 = nt * 8 + q * 2, b1 = b0 + 1;
        OT[(size_t)v0 * 32 + b0] = acc[nt][0] + bi0;
        OT[(size_t)v0 * 32 + b1] = acc[nt][1] + bi0;
        OT[(size_t)v1 * 32 + b0] = acc[nt][2] + bi1;
        OT[(size_t)v1 * 32 + b1] = acc[nt][3] + bi1;
    }
}

// ---------------- K2a: elementwise GRU h-update (transposed gates) ----------------
// grid 96, block 256. i = d*32 + b (coalesced gate loads).
__global__ void k2a_kernel() {
    int i = blockIdx.x * 256 + threadIdx.x;
    int d = i >> 5, b = i & 31;
    float r = sigf(g_giT[i] + g_ghT[i]);
    float z = sigf(g_giT[(Dd << 5) + i] + g_ghT[(Dd << 5) + i]);
    float n = tanhf(g_giT[(2 * Dd << 5) + i] + r * g_ghT[(2 * Dd << 5) + i]);
    int hi = b * Dd + d;
    g_h[hi] = (1.f - z) * n + z * g_h[hi];
}

// ---------------- K2h: h -> split bf16 (per step + once at init) ----------------
__global__ void k2h_kernel() {
    int i = blockIdx.x * 256 + threadIdx.x;
    float x = g_h[i];
    __nv_bfloat16 hi = __float2bfloat16(x);
    __nv_bfloat16 lo = __float2bfloat16(x - __bfloat162float(hi));
    g_hhb[i] = hi;
    g_hlb[i] = lo;
}

// ---------------- K2b: attention scores ----------------
__global__ void k2b_kernel(const float* __restrict__ enc, const int* __restrict__ ids) {
    __shared__ float hs[Dd];
    int b = blockIdx.y, xc = blockIdx.x;
    int t = threadIdx.x, lane = t & 31, w = t >> 5;
    for (int d = t; d < Dd; d += 256) hs[d] = g_h[(size_t)b * Dd + d];
    __syncthreads();
    #pragma unroll
    for (int i = 0; i < 4; i++) {
        int xi = xc * 32 + w * 4 + i;
        const float* er = enc + ((size_t)b * Xx + xi) * Dd;
        float s = 0.f;
        #pragma unroll
        for (int kk = 0; kk < 6; kk++) {
            float4 e4 = *(const float4*)(er + kk * 128 + lane * 4);
            float4 h4 = *(const float4*)(hs + kk * 128 + lane * 4);
            s += e4.x * h4.x + e4.y * h4.y + e4.z * h4.z + e4.w * h4.w;
        }
        #pragma unroll
        for (int o = 16; o; o >>= 1) s += __shfl_xor_sync(0xffffffffu, s, o);
        if (lane == 0)
            g_attn[b * Xx + xi] = (ids[b * Xx + xi] == 0) ? -1e9f : s;
    }
}

// ---------------- K2c: softmax over x ----------------
__global__ void k2c_kernel() {
    __shared__ float red[256];
    int b = blockIdx.x, t = threadIdx.x;
    float v = g_attn[b * Xx + t];
    red[t] = v; __syncthreads();
    for (int s2 = 128; s2; s2 >>= 1) { if (t < s2) red[t] = fmaxf(red[t], red[t + s2]); __syncthreads(); }
    float m = red[0]; __syncthreads();
    float ev = expf(v - m);
    red[t] = ev; __syncthreads();
    for (int s2 = 128; s2; s2 >>= 1) { if (t < s2) red[t] += red[t + s2]; __syncthreads(); }
    g_attn[b * Xx + t] = ev / red[0];
}

// ---------------- K2d: context = attn @ enc ----------------
__global__ void k2d_kernel(const float* __restrict__ enc) {
    __shared__ float s_at[Xx];
    int b = blockIdx.y, t = threadIdx.x;
    int d0 = blockIdx.x * 128;
    s_at[t] = g_attn[b * Xx + t];
    s_at[t + 128] = g_attn[b * Xx + t + 128];
    __syncthreads();
    const float* eb = enc + (size_t)b * Xx * Dd + d0 + t;
    float a0 = 0.f, a1 = 0.f, a2 = 0.f, a3 = 0.f;
    #pragma unroll 2
    for (int x = 0; x < Xx; x += 4) {
        a0 += s_at[x + 0] * eb[(size_t)(x + 0) * Dd];
        a1 += s_at[x + 1] * eb[(size_t)(x + 1) * Dd];
        a2 += s_at[x + 2] * eb[(size_t)(x + 2) * Dd];
        a3 += s_at[x + 3] * eb[(size_t)(x + 3) * Dd];
    }
    g_ctx[(size_t)b * Dd + d0 + t] = (a0 + a1) + (a2 + a3);
}

// ---------------- K3: HMMA split-bf16 GEMM, e = exp(emb @ h^T) ----------------
__global__ void __launch_bounds__(256, 2) k3_kernel() {
    extern __shared__ __align__(16) __nv_bfloat16 sm[];
    __shared__ float sSum[8][32];
    __shared__ unsigned long long sKey[8][32];
    int t = threadIdx.x, w = t >> 5, lane = t & 31;
    int q = lane & 3, r8 = lane >> 2;
    int blk = blockIdx.x, vbase = blk << 7;
    unsigned int sbase = s2u(sm);

    float acc[4][4];
    #pragma unroll
    for (int nt = 0; nt < 4; nt++)
        #pragma unroll
        for (int i = 0; i < 4; i++) acc[nt][i] = 0.f;

    int lr = t >> 2, lc = (t & 3) * 8;
    int hr = (t & 127) >> 2, hc = ((t & 127) & 3) * 8;
    const __nv_bfloat16* gA0h = g_ebh + (size_t)(vbase + lr) * Dd + lc;
    const __nv_bfloat16* gA1h = g_ebh + (size_t)(vbase + lr + 64) * Dd + lc;
    const __nv_bfloat16* gA0l = g_ebl + (size_t)(vbase + lr) * Dd + lc;
    const __nv_bfloat16* gA1l = g_ebl + (size_t)(vbase + lr + 64) * Dd + lc;
    const __nv_bfloat16* gH = (t < 128 ? g_hhb : g_hlb) + (size_t)hr * Dd + hc;
    unsigned int dA0 = (unsigned)((SA_H + lr * 40 + lc) * 2);
    unsigned int dA1 = (unsigned)((SA_H + (lr + 64) * 40 + lc) * 2);
    unsigned int dL0 = (unsigned)((SA_L + lr * 40 + lc) * 2);
    unsigned int dL1 = (unsigned)((SA_L + (lr + 64) * 40 + lc) * 2);
    unsigned int dH = (unsigned)(((t < 128 ? SH_H : SH_L) + hr * 40 + hc) * 2);

    {
        cpa16(sbase + dA0, gA0h);
        cpa16(sbase + dA1, gA1h);
        cpa16(sbase + dL0, gA0l);
        cpa16(sbase + dL1, gA1l);
        cpa16(sbase + dH, gH);
        asm volatile("cp.async.commit_group;" ::: "memory");
        asm volatile("cp.async.wait_group 0;" ::: "memory");
    }
    __syncthreads();

    for (int kc = 0; kc < NCH; kc++) {
        int buf = kc & 1;
        if (kc + 1 < NCH) {
            unsigned int nb = sbase + (buf ^ 1) * (SBUF * 2);
            int ko = (kc + 1) * 32;
            cpa16(nb + dA0, gA0h + ko);
            cpa16(nb + dA1, gA1h + ko);
            cpa16(nb + dL0, gA0l + ko);
            cpa16(nb + dL1, gA1l + ko);
            cpa16(nb + dH, gH + ko);
            asm volatile("cp.async.commit_group;" ::: "memory");
        }
        const __nv_bfloat16* Ah = sm + buf * SBUF + SA_H;
        const __nv_bfloat16* Al = sm + buf * SBUF + SA_L;
        const __nv_bfloat16* Hh = sm + buf * SBUF + SH_H;
        const __nv_bfloat16* Hl = sm + buf * SBUF + SH_L;
        int ar = w * 16 + r8;
        #pragma unroll
        for (int s = 0; s < 2; s++) {
            int k0 = s * 16, ac = k0 + q * 2;
            unsigned ah0 = *(const unsigned*)&Ah[ar * 40 + ac];
            unsigned ah1 = *(const unsigned*)&Ah[(ar + 8) * 40 + ac];
            unsigned ah2 = *(const unsigned*)&Ah[ar * 40 + ac + 8];
            unsigned ah3 = *(const unsigned*)&Ah[(ar + 8) * 40 + ac + 8];
            unsigned al0 = *(const unsigned*)&Al[ar * 40 + ac];
            unsigned al1 = *(const unsigned*)&Al[(ar + 8) * 40 + ac];
            unsigned al2 = *(const unsigned*)&Al[ar * 40 + ac + 8];
            unsigned al3 = *(const unsigned*)&Al[(ar + 8) * 40 + ac + 8];
            #pragma unroll
            for (int nt = 0; nt < 4; nt++) {
                int bn = (nt * 8 + r8) * 40 + k0 + q * 2;
                unsigned bh0 = *(const unsigned*)&Hh[bn];
                unsigned bh1 = *(const unsigned*)&Hh[bn + 8];
                unsigned bl0 = *(const unsigned*)&Hl[bn];
                unsigned bl1 = *(const unsigned*)&Hl[bn + 8];
                mma_bf16(acc[nt], ah0, ah1, ah2, ah3, bh0, bh1);
                mma_bf16(acc[nt], al0, al1, al2, al3, bh0, bh1);
                mma_bf16(acc[nt], ah0, ah1, ah2, ah3, bl0, bl1);
            }
        }
        if (kc + 1 < NCH)
            asm volatile("cp.async.wait_group 0;" ::: "memory");
        __syncthreads();
    }

    int v0 = vbase + w * 16 + r8, v1 = v0 + 8;
    bool ok0 = v0 < VV, ok1 = v1 < VV;
    #pragma unroll
    for (int nt = 0; nt < 4; nt++) {
        float e00 = ok0 ? __expf(acc[nt][0]) : 0.f;
        float e01 = ok0 ? __expf(acc[nt][1]) : 0.f;
        float e10 = ok1 ? __expf(acc[nt][2]) : 0.f;
        float e11 = ok1 ? __expf(acc[nt][3]) : 0.f;
        int b0 = nt * 8 + q * 2, b1 = b0 + 1;
        g_e[(size_t)b0 * VP + v0] = e00;
        g_e[(size_t)b1 * VP + v0] = e01;
        g_e[(size_t)b0 * VP + v1] = e10;
        g_e[(size_t)b1 * VP + v1] = e11;
        float s0 = e00 + e10, s1 = e01 + e11;
        unsigned long long k00 = ((unsigned long long)__float_as_uint(e00) << 32) | (unsigned)(~v0);
        unsigned long long k10 = ((unsigned long long)__float_as_uint(e10) << 32) | (unsigned)(~v1);
        unsigned long long k01 = ((unsigned long long)__float_as_uint(e01) << 32) | (unsigned)(~v0);
        unsigned long long k11 = ((unsigned long long)__float_as_uint(e11) << 32) | (unsigned)(~v1);
        unsigned long long key0 = k00 > k10 ? k00 : k10;
        unsigned long long key1 = k01 > k11 ? k01 : k11;
        #pragma unroll
        for (int o = 4; o <= 16; o <<= 1) {
            s0 += __shfl_xor_sync(0xffffffffu, s0, o);
            s1 += __shfl_xor_sync(0xffffffffu, s1, o);
            unsigned long long t0 = __shfl_xor_sync(0xffffffffu, key0, o);
            unsigned long long t1 = __shfl_xor_sync(0xffffffffu, key1, o);
            if (t0 > key0) key0 = t0;
            if (t1 > key1) key1 = t1;
        }
        if (r8 == 0) {
            sSum[w][b0] = s0; sSum[w][b1] = s1;
            sKey[w][b0] = key0; sKey[w][b1] = key1;
        }
    }
    __syncthreads();
    if (t < 32) {
        float s = 0.f;
        unsigned long long k = 0ull;
        #pragma unroll
        for (int w2 = 0; w2 < 8; w2++) {
            s += sSum[w2][t];
            if (sKey[w2][t] > k) k = sKey[w2][t];
        }
        g_psum[t * NB + blk] = s;
        g_pkey[t * NB + blk] = k;
    }
}

// ---------------- K4: p_gen; reduce partials; scatter writes; argmax; x_next -------
__global__ void k4_kernel(const float* __restrict__ emb, const int* __restrict__ ids,
                          const float* __restrict__ dec,
                          const float* __restrict__ w_gen, const float* __restrict__ b_gen,
                          float* __restrict__ out, int j, int kstep, int k0) {
    __shared__ float rf[256];
    __shared__ unsigned long long rk[256];
    __shared__ float s_at[Xx];
    __shared__ int s_ids[Xx];
    __shared__ int s_am;
    __shared__ float s_pg;
    int b = blockIdx.x, t = threadIdx.x;

    const float* xr = k0 ? (dec + ((size_t)b * Jj + j) * Dd) : (g_x + (size_t)b * Dd);
    float pgp = 0.f;
    for (int d = t; d < Dd; d += 256)
        pgp += w_gen[d] * g_h[(size_t)b * Dd + d]
             + w_gen[Dd + d] * xr[d]
             + w_gen[2 * Dd + d] * g_ctx[(size_t)b * Dd + d];
    rf[t] = pgp; __syncthreads();
    for (int s2 = 128; s2; s2 >>= 1) { if (t < s2) rf[t] += rf[t + s2]; __syncthreads(); }
    if (t == 0) { s_pg = sigf(rf[0] + b_gen[0]); g_pgen[b] = s_pg; }
    __syncthreads();
    float pg = s_pg;
    __syncthreads();

    rf[t] = (t < NB) ? g_psum[b * NB + t] : 0.f;
    rk[t] = (t < NB) ? g_pkey[b * NB + t] : 0ull;
    s_ids[t] = ids[b * Xx + t];
    s_at[t] = g_attn[b * Xx + t];
    __syncthreads();
    for (int s2 = 128; s2; s2 >>= 1) {
        if (t < s2) {
            rf[t] += rf[t + s2];
            if (rk[t + s2] > rk[t]) rk[t] = rk[t + s2];
        }
        __syncthreads();
    }
    float inv = 1.f / rf[0];
    int vd = ~(unsigned)(rk[0] & 0xffffffffu);
    if (t == 0) g_inv[b] = inv;
    __syncthreads();

    const float* erow = g_e + (size_t)b * VP;
    float* orow = out + (((size_t)b * Jj + j) * Kk + kstep) * VV;
    float one_m = 1.f - pg;

    float dval = pg * erow[vd] * inv;
    unsigned long long best =
        ((unsigned long long)__float_as_uint(dval) << 32) | (unsigned)(~vd);
    {
        int v = s_ids[t];
        float a = 0.f;
        #pragma unroll 4
        for (int x2 = 0; x2 < Xx; x2++) a += (s_ids[x2] == v) ? s_at[x2] : 0.f;
        float full = pg * erow[v] * inv + one_m * a;
        orow[v] = full;
        unsigned long long key =
            ((unsigned long long)__float_as_uint(full) << 32) | (unsigned)(~v);
        if (key > best) best = key;
    }
    rk[t] = best; __syncthreads();
    for (int s2 = 128; s2; s2 >>= 1) {
        if (t < s2 && rk[t + s2] > rk[t]) rk[t] = rk[t + s2];
        __syncthreads();
    }
    if (t == 0) s_am = ~(unsigned)(rk[0] & 0xffffffffu);
    __syncthreads();
    int am = s_am;
    for (int d = t; d < Dd; d += 256)
        g_x[(size_t)b * Dd + d] = emb[(size_t)am * Dd + d];
}

// ---------------- K5w: dense output write ----------------
__global__ void k5w_kernel(float* __restrict__ out, int j, int kstep) {
    int b = blockIdx.y, t = threadIdx.x;
    int v0 = blockIdx.x * 1024 + t * 4;
    if (v0 >= VV) return;
    float sc = g_pgen[b] * g_inv[b];
    const float* erow = g_e + (size_t)b * VP;
    float* orow = out + (((size_t)b * Jj + j) * Kk + kstep) * VV;
    unsigned m = (g_bit[b * BW + (v0 >> 5)] >> (v0 & 31)) & 0xFu;
    if (v0 + 3 < VV) {
        float4 e4 = *(const float4*)(erow + v0);
        float o0 = sc * e4.x, o1 = sc * e4.y, o2 = sc * e4.z, o3 = sc * e4.w;
        if (m == 0u) {
            *(float2*)(orow + v0)     = make_float2(o0, o1);
            *(float2*)(orow + v0 + 2) = make_float2(o2, o3);
        } else {
            if (!(m & 1u)) orow[v0 + 0] = o0;
            if (!(m & 2u)) orow[v0 + 1] = o1;
            if (!(m & 4u)) orow[v0 + 2] = o2;
            if (!(m & 8u)) orow[v0 + 3] = o3;
        }
    } else {
        for (int v = v0; v < VV; v++)
            if (!((m >> (v - v0)) & 1u)) orow[v] = sc * erow[v];
    }
}

extern "C" void kernel_launch(void* const* d_in, const int* in_sizes, int n_in,
                              void* d_out, int out_size) {
    const float* dec    = (const float*)d_in[0];
    const float* hidden = (const float*)d_in[1];
    const float* enc    = (const float*)d_in[2];
    const int*   ids    = (const int*)  d_in[3];
    int ei = (in_sizes[4] <= 16) ? 5 : 4;
    const float* emb   = (const float*)d_in[ei + 0];
    const float* w_ih  = (const float*)d_in[ei + 1];
    const float* w_hh  = (const float*)d_in[ei + 2];
    const float* b_ih  = (const float*)d_in[ei + 3];
    const float* b_hh  = (const float*)d_in[ei + 4];
    const float* w_gen = (const float*)d_in[ei + 5];
    const float* b_gen = (const float*)d_in[ei + 6];
    float* out = (float*)d_out;

    const int SMEM3 = SBUF * 2 * 2;  // 51200 bytes
    cudaFuncSetAttribute(k3_kernel, cudaFuncAttributeMaxDynamicSharedMemorySize, SMEM3);
    cudaFuncSetAttribute(k1h_kernel, cudaFuncAttributeMaxDynamicSharedMemorySize, SMEM3);

    init_kernel<<<(Bz * Dd + 255) / 256, 256>>>(hidden);
    k2h_kernel<<<96, 256>>>();   // seed split of initial h for step 0's k1h
    bit_kernel<<<Bz, Xx>>>(ids);
    k0e_kernel<<<(int)(((size_t)VP * Dd) / 4096), 256>>>(emb);
    k0w_kernel<<<1728, 256>>>(w_ih, 0);
    k0w_kernel<<<1728, 256>>>(w_hh, 1);
    for (int j = 0; j < Jj; j++) {
        for (int k = 0; k < Kk; k++) {
            int k0 = (k == 0);
            k2x_kernel<<<96, 256>>>(dec, j, k0);
            k1h_kernel<<<dim3(18, 2), 256, SMEM3>>>(b_ih, b_hh);
            k2a_kernel<<<96, 256>>>();
            k2h_kernel<<<96, 256>>>();
            k2b_kernel<<<dim3(8, Bz), 256>>>(enc, ids);
            k2c_kernel<<<Bz, 256>>>();
            k2d_kernel<<<dim3(6, Bz), 128>>>(enc);
            k3_kernel<<<NB, 256, SMEM3>>>();
            k4_kernel<<<Bz, 256>>>(emb, ids, dec, w_gen, b_gen, out, j, k, k0);
            k5w_kernel<<<dim3(30, Bz), 256>>>(out, j, k);
        }
    }
}

// round 11
// speedup vs baseline: 5.3596x; 1.1550x over previous
#include <cuda_runtime.h>
#include <cuda_bf16.h>
#include <math.h>

#define Bz 32
#define Dd 768
#define D3 2304
#define Xx 256
#define VV 30522
#define VP 30720          // 240*128 padded vocab
#define NB 240            // K3 grid (v-blocks of 128)
#define BW 960
#define Jj 4
#define Kk 8
#define NCH 24            // K3 k-chunks of 32
#define NCHH 12           // k1h k-chunks per z-half
// smem element offsets (bf16 elems), rows padded to 40 (80B, conflict-free)
#define SA_H 0
#define SA_L 5120
#define SH_H 10240
#define SH_L 11520
#define SBUF 12800        // elems per buffer (25600 B)

// ---------------- persistent device scratch ----------------
__device__ float g_h[Bz * Dd];
__device__ float g_x[Bz * Dd];
__device__ float g_ctx[Bz * Dd];
__device__ float g_giT[D3 * Bz];    // gate partials, k-half 0 (with bias)
__device__ float g_giT2[D3 * Bz];   // k-half 1
__device__ float g_ghT[D3 * Bz];
__device__ float g_ghT2[D3 * Bz];
__device__ float g_attn[Bz * Xx];    // raw masked scores
__device__ float g_attn_n[Bz * Xx];  // normalized attn
__device__ float g_pgen[Bz];
__device__ float g_inv[Bz];
__device__ __align__(16) float g_e[Bz * VP];
__device__ float g_psum[Bz * NB];
__device__ unsigned long long g_pkey[Bz * NB];
__device__ unsigned int g_bit[Bz * BW];
// split-bf16 emb [VP][768]
__device__ __align__(16) __nv_bfloat16 g_ebh[(size_t)VP * Dd];
__device__ __align__(16) __nv_bfloat16 g_ebl[(size_t)VP * Dd];
// split-bf16 weights [2304][768]
__device__ __align__(16) __nv_bfloat16 g_wih_h[(size_t)D3 * Dd];
__device__ __align__(16) __nv_bfloat16 g_wih_l[(size_t)D3 * Dd];
__device__ __align__(16) __nv_bfloat16 g_whh_h[(size_t)D3 * Dd];
__device__ __align__(16) __nv_bfloat16 g_whh_l[(size_t)D3 * Dd];
// split-bf16 h and x [32][768]
__device__ __align__(16) __nv_bfloat16 g_hhb[Bz * Dd];
__device__ __align__(16) __nv_bfloat16 g_hlb[Bz * Dd];
__device__ __align__(16) __nv_bfloat16 g_xhb[Bz * Dd];
__device__ __align__(16) __nv_bfloat16 g_xlb[Bz * Dd];

__device__ __forceinline__ float sigf(float x) { return 1.0f / (1.0f + expf(-x)); }

__device__ __forceinline__ unsigned int s2u(const void* p) {
    unsigned int a;
    asm("{ .reg .u64 t; cvta.to.shared.u64 t, %1; cvt.u32.u64 %0, t; }" : "=r"(a) : "l"(p));
    return a;
}
__device__ __forceinline__ void cpa16(unsigned int d, const void* s) {
    asm volatile("cp.async.cg.shared.global [%0], [%1], 16;" :: "r"(d), "l"(s) : "memory");
}
__device__ __forceinline__ void mma_bf16(float* d, unsigned a0, unsigned a1,
                                         unsigned a2, unsigned a3,
                                         unsigned b0, unsigned b1) {
    asm volatile(
        "mma.sync.aligned.m16n8k16.row.col.f32.bf16.bf16.f32 "
        "{%0,%1,%2,%3}, {%4,%5,%6,%7}, {%8,%9}, {%0,%1,%2,%3};"
        : "+f"(d[0]), "+f"(d[1]), "+f"(d[2]), "+f"(d[3])
        : "r"(a0), "r"(a1), "r"(a2), "r"(a3), "r"(b0), "r"(b1));
}

// ---------------- init ----------------
__global__ void init_kernel(const float* __restrict__ hidden) {
    int i = blockIdx.x * 256 + threadIdx.x;
    if (i < Bz * Dd) {
        float x = hidden[i];
        g_h[i] = x;
        __nv_bfloat16 hi = __float2bfloat16(x);
        g_hhb[i] = hi;
        g_hlb[i] = __float2bfloat16(x - __bfloat162float(hi));
    }
}
__global__ void bit_kernel(const int* __restrict__ ids) {
    int b = blockIdx.x, t = threadIdx.x;
    int id = ids[b * Xx + t];
    atomicOr(&g_bit[b * BW + (id >> 5)], 1u << (id & 31));
}
// emb -> split bf16 row-major. grid 5760, block 256; 16 elems/thread.
__global__ void k0e_kernel(const float* __restrict__ emb) {
    size_t base = ((size_t)blockIdx.x * 256 + threadIdx.x) * 16;
    int v = (int)(base / Dd);
    bool valid = v < VV;
    const float* src = emb + base;
    #pragma unroll
    for (int i = 0; i < 4; i++) {
        float4 f = valid ? *(const float4*)(src + i * 4) : make_float4(0.f, 0.f, 0.f, 0.f);
        float vs[4] = {f.x, f.y, f.z, f.w};
        #pragma unroll
        for (int u = 0; u < 4; u++) {
            __nv_bfloat16 hi = __float2bfloat16(vs[u]);
            __nv_bfloat16 lo = __float2bfloat16(vs[u] - __bfloat162float(hi));
            g_ebh[base + i * 4 + u] = hi;
            g_ebl[base + i * 4 + u] = lo;
        }
    }
}
// weights -> split bf16. grid 1728, block 256, 4 elems/thread. which: 0=ih, 1=hh.
__global__ void k0w_kernel(const float* __restrict__ w, int which) {
    size_t base = ((size_t)blockIdx.x * 256 + threadIdx.x) * 4;
    __nv_bfloat16* oh = which ? g_whh_h : g_wih_h;
    __nv_bfloat16* ol = which ? g_whh_l : g_wih_l;
    float4 f = *(const float4*)(w + base);
    float vs[4] = {f.x, f.y, f.z, f.w};
    #pragma unroll
    for (int u = 0; u < 4; u++) {
        __nv_bfloat16 hi = __float2bfloat16(vs[u]);
        __nv_bfloat16 lo = __float2bfloat16(vs[u] - __bfloat162float(hi));
        oh[base + u] = hi;
        ol[base + u] = lo;
    }
}

// ---------------- K2x: x -> split bf16 from dec (k==0 steps only) ----------------
__global__ void k2x_kernel(const float* __restrict__ dec, int j) {
    int i = blockIdx.x * 256 + threadIdx.x;   // i = b*Dd + d
    int b = i / Dd, d = i - b * Dd;
    float x = dec[((size_t)b * Jj + j) * Dd + d];
    __nv_bfloat16 hi = __float2bfloat16(x);
    g_xhb[i] = hi;
    g_xlb[i] = __float2bfloat16(x - __bfloat162float(hi));
}

// ---------------- K1h: HMMA gate GEMMs, K-split across blockIdx.z ----------------
// grid (18, 2, 2), block 256, dyn smem 51200B. Per block: 128 c-rows x 32 b, 12 chunks.
__global__ void __launch_bounds__(256, 2) k1h_kernel(const float* __restrict__ b_ih,
                                                     const float* __restrict__ b_hh) {
    extern __shared__ __align__(16) __nv_bfloat16 sm[];
    int t = threadIdx.x, w = t >> 5, lane = t & 31;
    int q = lane & 3, r8 = lane >> 2;
    int vbase = blockIdx.x << 7;
    int z = blockIdx.z;
    int ko0 = z * (NCHH * 32);
    unsigned int sbase = s2u(sm);

    const __nv_bfloat16 *Wh, *Wl, *Bh, *Bl;
    const float* bias;
    float* OT;
    if (blockIdx.y == 0) {
        Wh = g_wih_h; Wl = g_wih_l; Bh = g_xhb; Bl = g_xlb; bias = b_ih;
        OT = z ? g_giT2 : g_giT;
    } else {
        Wh = g_whh_h; Wl = g_whh_l; Bh = g_hhb; Bl = g_hlb; bias = b_hh;
        OT = z ? g_ghT2 : g_ghT;
    }

    float acc[4][4];
    #pragma unroll
    for (int nt = 0; nt < 4; nt++)
        #pragma unroll
        for (int i = 0; i < 4; i++) acc[nt][i] = 0.f;

    int lr = t >> 2, lc = (t & 3) * 8;
    int hr = (t & 127) >> 2, hc = ((t & 127) & 3) * 8;
    const __nv_bfloat16* gA0h = Wh + (size_t)(vbase + lr) * Dd + lc + ko0;
    const __nv_bfloat16* gA1h = Wh + (size_t)(vbase + lr + 64) * Dd + lc + ko0;
    const __nv_bfloat16* gA0l = Wl + (size_t)(vbase + lr) * Dd + lc + ko0;
    const __nv_bfloat16* gA1l = Wl + (size_t)(vbase + lr + 64) * Dd + lc + ko0;
    const __nv_bfloat16* gH = (t < 128 ? Bh : Bl) + (size_t)hr * Dd + hc + ko0;
    unsigned int dA0 = (unsigned)((SA_H + lr * 40 + lc) * 2);
    unsigned int dA1 = (unsigned)((SA_H + (lr + 64) * 40 + lc) * 2);
    unsigned int dL0 = (unsigned)((SA_L + lr * 40 + lc) * 2);
    unsigned int dL1 = (unsigned)((SA_L + (lr + 64) * 40 + lc) * 2);
    unsigned int dH = (unsigned)(((t < 128 ? SH_H : SH_L) + hr * 40 + hc) * 2);

    {
        cpa16(sbase + dA0, gA0h);
        cpa16(sbase + dA1, gA1h);
        cpa16(sbase + dL0, gA0l);
        cpa16(sbase + dL1, gA1l);
        cpa16(sbase + dH, gH);
        asm volatile("cp.async.commit_group;" ::: "memory");
        asm volatile("cp.async.wait_group 0;" ::: "memory");
    }
    __syncthreads();

    for (int kc = 0; kc < NCHH; kc++) {
        int buf = kc & 1;
        if (kc + 1 < NCHH) {
            unsigned int nb = sbase + (buf ^ 1) * (SBUF * 2);
            int ko = (kc + 1) * 32;
            cpa16(nb + dA0, gA0h + ko);
            cpa16(nb + dA1, gA1h + ko);
            cpa16(nb + dL0, gA0l + ko);
            cpa16(nb + dL1, gA1l + ko);
            cpa16(nb + dH, gH + ko);
            asm volatile("cp.async.commit_group;" ::: "memory");
        }
        const __nv_bfloat16* Ah = sm + buf * SBUF + SA_H;
        const __nv_bfloat16* Al = sm + buf * SBUF + SA_L;
        const __nv_bfloat16* Hh = sm + buf * SBUF + SH_H;
        const __nv_bfloat16* Hl = sm + buf * SBUF + SH_L;
        int ar = w * 16 + r8;
        #pragma unroll
        for (int s = 0; s < 2; s++) {
            int k0 = s * 16, ac = k0 + q * 2;
            unsigned ah0 = *(const unsigned*)&Ah[ar * 40 + ac];
            unsigned ah1 = *(const unsigned*)&Ah[(ar + 8) * 40 + ac];
            unsigned ah2 = *(const unsigned*)&Ah[ar * 40 + ac + 8];
            unsigned ah3 = *(const unsigned*)&Ah[(ar + 8) * 40 + ac + 8];
            unsigned al0 = *(const unsigned*)&Al[ar * 40 + ac];
            unsigned al1 = *(const unsigned*)&Al[(ar + 8) * 40 + ac];
            unsigned al2 = *(const unsigned*)&Al[ar * 40 + ac + 8];
            unsigned al3 = *(const unsigned*)&Al[(ar + 8) * 40 + ac + 8];
            #pragma unroll
            for (int nt = 0; nt < 4; nt++) {
                int bn = (nt * 8 + r8) * 40 + k0 + q * 2;
                unsigned bh0 = *(const unsigned*)&Hh[bn];
                unsigned bh1 = *(const unsigned*)&Hh[bn + 8];
                unsigned bl0 = *(const unsigned*)&Hl[bn];
                unsigned bl1 = *(const unsigned*)&Hl[bn + 8];
                mma_bf16(acc[nt], ah0, ah1, ah2, ah3, bh0, bh1);
                mma_bf16(acc[nt], al0, al1, al2, al3, bh0, bh1);
                mma_bf16(acc[nt], ah0, ah1, ah2, ah3, bl0, bl1);
            }
        }
        if (kc + 1 < NCHH)
            asm volatile("cp.async.wait_group 0;" ::: "memory");
        __syncthreads();
    }

    int v0 = vbase + w * 16 + r8, v1 = v0 + 8;
    float bi0 = z ? 0.f : bias[v0];
    float bi1 = z ? 0.f : bias[v1];
    #pragma unroll
    for (int nt = 0; nt < 4; nt++) {
        int b0 = nt * 8 + q * 2, b1 = b0 + 1;
        OT[(size_t)v0 * 32 + b0] = acc[nt][0] + bi0;
        OT[(size_t)v0 * 32 + b1] = acc[nt][1] + bi0;
        OT[(size_t)v1 * 32 + b0] = acc[nt][2] + bi1;
        OT[(size_t)v1 * 32 + b1] = acc[nt][3] + bi1;
    }
}

// ---------------- K2ah: GRU h-update (sums k-halves) + bf16 split ----------------
// grid 96, block 256. i = d*32 + b.
__global__ void k2ah_kernel() {
    int i = blockIdx.x * 256 + threadIdx.x;
    int d = i >> 5, b = i & 31;
    float gi0 = g_giT[i] + g_giT2[i];
    float gh0 = g_ghT[i] + g_ghT2[i];
    float gi1 = g_giT[(Dd << 5) + i] + g_giT2[(Dd << 5) + i];
    float gh1 = g_ghT[(Dd << 5) + i] + g_ghT2[(Dd << 5) + i];
    float gi2 = g_giT[(2 * Dd << 5) + i] + g_giT2[(2 * Dd << 5) + i];
    float gh2 = g_ghT[(2 * Dd << 5) + i] + g_ghT2[(2 * Dd << 5) + i];
    float r = sigf(gi0 + gh0);
    float z = sigf(gi1 + gh1);
    float n = tanhf(gi2 + r * gh2);
    int hi_ = b * Dd + d;
    float h = (1.f - z) * n + z * g_h[hi_];
    g_h[hi_] = h;
    __nv_bfloat16 hh = __float2bfloat16(h);
    g_hhb[hi_] = hh;
    g_hlb[hi_] = __float2bfloat16(h - __bfloat162float(hh));
}

// ---------------- K2b: attention scores (raw, masked) ----------------
__global__ void k2b_kernel(const float* __restrict__ enc, const int* __restrict__ ids) {
    __shared__ float hs[Dd];
    int b = blockIdx.y, xc = blockIdx.x;
    int t = threadIdx.x, lane = t & 31, w = t >> 5;
    for (int d = t; d < Dd; d += 256) hs[d] = g_h[(size_t)b * Dd + d];
    __syncthreads();
    #pragma unroll
    for (int i = 0; i < 4; i++) {
        int xi = xc * 32 + w * 4 + i;
        const float* er = enc + ((size_t)b * Xx + xi) * Dd;
        float s = 0.f;
        #pragma unroll
        for (int kk = 0; kk < 6; kk++) {
            float4 e4 = *(const float4*)(er + kk * 128 + lane * 4);
            float4 h4 = *(const float4*)(hs + kk * 128 + lane * 4);
            s += e4.x * h4.x + e4.y * h4.y + e4.z * h4.z + e4.w * h4.w;
        }
        #pragma unroll
        for (int o = 16; o; o >>= 1) s += __shfl_xor_sync(0xffffffffu, s, o);
        if (lane == 0)
            g_attn[b * Xx + xi] = (ids[b * Xx + xi] == 0) ? -1e9f : s;
    }
}

// ---------------- K2d: local softmax + context = attn @ enc ----------------
// grid (6, 32), block 128. Every block recomputes the softmax identically;
// block x==0 also publishes normalized attn to g_attn_n.
__global__ void k2d_kernel(const float* __restrict__ enc) {
    __shared__ float sc[Xx];
    __shared__ float s_at[Xx];
    __shared__ float red[128];
    int b = blockIdx.y, t = threadIdx.x;
    int d0 = blockIdx.x * 128;
    sc[t] = g_attn[b * Xx + t];
    sc[t + 128] = g_attn[b * Xx + t + 128];
    __syncthreads();
    red[t] = fmaxf(sc[t], sc[t + 128]);
    __syncthreads();
    for (int s2 = 64; s2; s2 >>= 1) { if (t < s2) red[t] = fmaxf(red[t], red[t + s2]); __syncthreads(); }
    float m = red[0];
    __syncthreads();
    float e0 = expf(sc[t] - m), e1 = expf(sc[t + 128] - m);
    red[t] = e0 + e1;
    __syncthreads();
    for (int s2 = 64; s2; s2 >>= 1) { if (t < s2) red[t] += red[t + s2]; __syncthreads(); }
    float inv = 1.f / red[0];
    float a0_ = e0 * inv, a1_ = e1 * inv;
    s_at[t] = a0_;
    s_at[t + 128] = a1_;
    if (blockIdx.x == 0) {
        g_attn_n[b * Xx + t] = a0_;
        g_attn_n[b * Xx + t + 128] = a1_;
    }
    __syncthreads();
    const float* eb = enc + (size_t)b * Xx * Dd + d0 + t;
    float a0 = 0.f, a1 = 0.f, a2 = 0.f, a3 = 0.f;
    #pragma unroll 2
    for (int x = 0; x < Xx; x += 4) {
        a0 += s_at[x + 0] * eb[(size_t)(x + 0) * Dd];
        a1 += s_at[x + 1] * eb[(size_t)(x + 1) * Dd];
        a2 += s_at[x + 2] * eb[(size_t)(x + 2) * Dd];
        a3 += s_at[x + 3] * eb[(size_t)(x + 3) * Dd];
    }
    g_ctx[(size_t)b * Dd + d0 + t] = (a0 + a1) + (a2 + a3);
}

// ---------------- K3: HMMA split-bf16 GEMM, e = exp(emb @ h^T) ----------------
__global__ void __launch_bounds__(256, 2) k3_kernel() {
    extern __shared__ __align__(16) __nv_bfloat16 sm[];
    __shared__ float sSum[8][32];
    __shared__ unsigned long long sKey[8][32];
    int t = threadIdx.x, w = t >> 5, lane = t & 31;
    int q = lane & 3, r8 = lane >> 2;
    int blk = blockIdx.x, vbase = blk << 7;
    unsigned int sbase = s2u(sm);

    float acc[4][4];
    #pragma unroll
    for (int nt = 0; nt < 4; nt++)
        #pragma unroll
        for (int i = 0; i < 4; i++) acc[nt][i] = 0.f;

    int lr = t >> 2, lc = (t & 3) * 8;
    int hr = (t & 127) >> 2, hc = ((t & 127) & 3) * 8;
    const __nv_bfloat16* gA0h = g_ebh + (size_t)(vbase + lr) * Dd + lc;
    const __nv_bfloat16* gA1h = g_ebh + (size_t)(vbase + lr + 64) * Dd + lc;
    const __nv_bfloat16* gA0l = g_ebl + (size_t)(vbase + lr) * Dd + lc;
    const __nv_bfloat16* gA1l = g_ebl + (size_t)(vbase + lr + 64) * Dd + lc;
    const __nv_bfloat16* gH = (t < 128 ? g_hhb : g_hlb) + (size_t)hr * Dd + hc;
    unsigned int dA0 = (unsigned)((SA_H + lr * 40 + lc) * 2);
    unsigned int dA1 = (unsigned)((SA_H + (lr + 64) * 40 + lc) * 2);
    unsigned int dL0 = (unsigned)((SA_L + lr * 40 + lc) * 2);
    unsigned int dL1 = (unsigned)((SA_L + (lr + 64) * 40 + lc) * 2);
    unsigned int dH = (unsigned)(((t < 128 ? SH_H : SH_L) + hr * 40 + hc) * 2);

    {
        cpa16(sbase + dA0, gA0h);
        cpa16(sbase + dA1, gA1h);
        cpa16(sbase + dL0, gA0l);
        cpa16(sbase + dL1, gA1l);
        cpa16(sbase + dH, gH);
        asm volatile("cp.async.commit_group;" ::: "memory");
        asm volatile("cp.async.wait_group 0;" ::: "memory");
    }
    __syncthreads();

    for (int kc = 0; kc < NCH; kc++) {
        int buf = kc & 1;
        if (kc + 1 < NCH) {
            unsigned int nb = sbase + (buf ^ 1) * (SBUF * 2);
            int ko = (kc + 1) * 32;
            cpa16(nb + dA0, gA0h + ko);
            cpa16(nb + dA1, gA1h + ko);
            cpa16(nb + dL0, gA0l + ko);
            cpa16(nb + dL1, gA1l + ko);
            cpa16(nb + dH, gH + ko);
            asm volatile("cp.async.commit_group;" ::: "memory");
        }
        const __nv_bfloat16* Ah = sm + buf * SBUF + SA_H;
        const __nv_bfloat16* Al = sm + buf * SBUF + SA_L;
        const __nv_bfloat16* Hh = sm + buf * SBUF + SH_H;
        const __nv_bfloat16* Hl = sm + buf * SBUF + SH_L;
        int ar = w * 16 + r8;
        #pragma unroll
        for (int s = 0; s < 2; s++) {
            int k0 = s * 16, ac = k0 + q * 2;
            unsigned ah0 = *(const unsigned*)&Ah[ar * 40 + ac];
            unsigned ah1 = *(const unsigned*)&Ah[(ar + 8) * 40 + ac];
            unsigned ah2 = *(const unsigned*)&Ah[ar * 40 + ac + 8];
            unsigned ah3 = *(const unsigned*)&Ah[(ar + 8) * 40 + ac + 8];
            unsigned al0 = *(const unsigned*)&Al[ar * 40 + ac];
            unsigned al1 = *(const unsigned*)&Al[(ar + 8) * 40 + ac];
            unsigned al2 = *(const unsigned*)&Al[ar * 40 + ac + 8];
            unsigned al3 = *(const unsigned*)&Al[(ar + 8) * 40 + ac + 8];
            #pragma unroll
            for (int nt = 0; nt < 4; nt++) {
                int bn = (nt * 8 + r8) * 40 + k0 + q * 2;
                unsigned bh0 = *(const unsigned*)&Hh[bn];
                unsigned bh1 = *(const unsigned*)&Hh[bn + 8];
                unsigned bl0 = *(const unsigned*)&Hl[bn];
                unsigned bl1 = *(const unsigned*)&Hl[bn + 8];
                mma_bf16(acc[nt], ah0, ah1, ah2, ah3, bh0, bh1);
                mma_bf16(acc[nt], al0, al1, al2, al3, bh0, bh1);
                mma_bf16(acc[nt], ah0, ah1, ah2, ah3, bl0, bl1);
            }
        }
        if (kc + 1 < NCH)
            asm volatile("cp.async.wait_group 0;" ::: "memory");
        __syncthreads();
    }

    int v0 = vbase + w * 16 + r8, v1 = v0 + 8;
    bool ok0 = v0 < VV, ok1 = v1 < VV;
    #pragma unroll
    for (int nt = 0; nt < 4; nt++) {
        float e00 = ok0 ? __expf(acc[nt][0]) : 0.f;
        float e01 = ok0 ? __expf(acc[nt][1]) : 0.f;
        float e10 = ok1 ? __expf(acc[nt][2]) : 0.f;
        float e11 = ok1 ? __expf(acc[nt][3]) : 0.f;
        int b0 = nt * 8 + q * 2, b1 = b0 + 1;
        g_e[(size_t)b0 * VP + v0] = e00;
        g_e[(size_t)b1 * VP + v0] = e01;
        g_e[(size_t)b0 * VP + v1] = e10;
        g_e[(size_t)b1 * VP + v1] = e11;
        float s0 = e00 + e10, s1 = e01 + e11;
        unsigned long long k00 = ((unsigned long long)__float_as_uint(e00) << 32) | (unsigned)(~v0);
        unsigned long long k10 = ((unsigned long long)__float_as_uint(e10) << 32) | (unsigned)(~v1);
        unsigned long long k01 = ((unsigned long long)__float_as_uint(e01) << 32) | (unsigned)(~v0);
        unsigned long long k11 = ((unsigned long long)__float_as_uint(e11) << 32) | (unsigned)(~v1);
        unsigned long long key0 = k00 > k10 ? k00 : k10;
        unsigned long long key1 = k01 > k11 ? k01 : k11;
        #pragma unroll
        for (int o = 4; o <= 16; o <<= 1) {
            s0 += __shfl_xor_sync(0xffffffffu, s0, o);
            s1 += __shfl_xor_sync(0xffffffffu, s1, o);
            unsigned long long t0 = __shfl_xor_sync(0xffffffffu, key0, o);
            unsigned long long t1 = __shfl_xor_sync(0xffffffffu, key1, o);
            if (t0 > key0) key0 = t0;
            if (t1 > key1) key1 = t1;
        }
        if (r8 == 0) {
            sSum[w][b0] = s0; sSum[w][b1] = s1;
            sKey[w][b0] = key0; sKey[w][b1] = key1;
        }
    }
    __syncthreads();
    if (t < 32) {
        float s = 0.f;
        unsigned long long k = 0ull;
        #pragma unroll
        for (int w2 = 0; w2 < 8; w2++) {
            s += sSum[w2][t];
            if (sKey[w2][t] > k) k = sKey[w2][t];
        }
        g_psum[t * NB + blk] = s;
        g_pkey[t * NB + blk] = k;
    }
}

// ---------------- K4: p_gen; reduce partials; scatter; argmax; x_next (+split) ----
__global__ void k4_kernel(const float* __restrict__ emb, const int* __restrict__ ids,
                          const float* __restrict__ dec,
                          const float* __restrict__ w_gen, const float* __restrict__ b_gen,
                          float* __restrict__ out, int j, int kstep, int k0) {
    __shared__ float rf[256];
    __shared__ unsigned long long rk[256];
    __shared__ float s_at[Xx];
    __shared__ int s_ids[Xx];
    __shared__ int s_am;
    __shared__ float s_pg;
    int b = blockIdx.x, t = threadIdx.x;

    const float* xr = k0 ? (dec + ((size_t)b * Jj + j) * Dd) : (g_x + (size_t)b * Dd);
    float pgp = 0.f;
    for (int d = t; d < Dd; d += 256)
        pgp += w_gen[d] * g_h[(size_t)b * Dd + d]
             + w_gen[Dd + d] * xr[d]
             + w_gen[2 * Dd + d] * g_ctx[(size_t)b * Dd + d];
    rf[t] = pgp; __syncthreads();
    for (int s2 = 128; s2; s2 >>= 1) { if (t < s2) rf[t] += rf[t + s2]; __syncthreads(); }
    if (t == 0) { s_pg = sigf(rf[0] + b_gen[0]); g_pgen[b] = s_pg; }
    __syncthreads();
    float pg = s_pg;
    __syncthreads();

    rf[t] = (t < NB) ? g_psum[b * NB + t] : 0.f;
    rk[t] = (t < NB) ? g_pkey[b * NB + t] : 0ull;
    s_ids[t] = ids[b * Xx + t];
    s_at[t] = g_attn_n[b * Xx + t];
    __syncthreads();
    for (int s2 = 128; s2; s2 >>= 1) {
        if (t < s2) {
            rf[t] += rf[t + s2];
            if (rk[t + s2] > rk[t]) rk[t] = rk[t + s2];
        }
        __syncthreads();
    }
    float inv = 1.f / rf[0];
    int vd = ~(unsigned)(rk[0] & 0xffffffffu);
    if (t == 0) g_inv[b] = inv;
    __syncthreads();

    const float* erow = g_e + (size_t)b * VP;
    float* orow = out + (((size_t)b * Jj + j) * Kk + kstep) * VV;
    float one_m = 1.f - pg;

    float dval = pg * erow[vd] * inv;
    unsigned long long best =
        ((unsigned long long)__float_as_uint(dval) << 32) | (unsigned)(~vd);
    {
        int v = s_ids[t];
        float a = 0.f;
        #pragma unroll 4
        for (int x2 = 0; x2 < Xx; x2++) a += (s_ids[x2] == v) ? s_at[x2] : 0.f;
        float full = pg * erow[v] * inv + one_m * a;
        orow[v] = full;
        unsigned long long key =
            ((unsigned long long)__float_as_uint(full) << 32) | (unsigned)(~v);
        if (key > best) best = key;
    }
    rk[t] = best; __syncthreads();
    for (int s2 = 128; s2; s2 >>= 1) {
        if (t < s2 && rk[t + s2] > rk[t]) rk[t] = rk[t + s2];
        __syncthreads();
    }
    if (t == 0) s_am = ~(unsigned)(rk[0] & 0xffffffffu);
    __syncthreads();
    int am = s_am;
    for (int d = t; d < Dd; d += 256) {
        float xv = emb[(size_t)am * Dd + d];
        int xi = b * Dd + d;
        g_x[xi] = xv;
        __nv_bfloat16 hi = __float2bfloat16(xv);
        g_xhb[xi] = hi;
        g_xlb[xi] = __float2bfloat16(xv - __bfloat162float(hi));
    }
}

// ---------------- K5w: dense output write ----------------
__global__ void k5w_kernel(float* __restrict__ out, int j, int kstep) {
    int b = blockIdx.y, t = threadIdx.x;
    int v0 = blockIdx.x * 1024 + t * 4;
    if (v0 >= VV) return;
    float sc = g_pgen[b] * g_inv[b];
    const float* erow = g_e + (size_t)b * VP;
    float* orow = out + (((size_t)b * Jj + j) * Kk + kstep) * VV;
    unsigned m = (g_bit[b * BW + (v0 >> 5)] >> (v0 & 31)) & 0xFu;
    if (v0 + 3 < VV) {
        float4 e4 = *(const float4*)(erow + v0);
        float o0 = sc * e4.x, o1 = sc * e4.y, o2 = sc * e4.z, o3 = sc * e4.w;
        if (m == 0u) {
            *(float2*)(orow + v0)     = make_float2(o0, o1);
            *(float2*)(orow + v0 + 2) = make_float2(o2, o3);
        } else {
            if (!(m & 1u)) orow[v0 + 0] = o0;
            if (!(m & 2u)) orow[v0 + 1] = o1;
            if (!(m & 4u)) orow[v0 + 2] = o2;
            if (!(m & 8u)) orow[v0 + 3] = o3;
        }
    } else {
        for (int v = v0; v < VV; v++)
            if (!((m >> (v - v0)) & 1u)) orow[v] = sc * erow[v];
    }
}

extern "C" void kernel_launch(void* const* d_in, const int* in_sizes, int n_in,
                              void* d_out, int out_size) {
    const float* dec    = (const float*)d_in[0];
    const float* hidden = (const float*)d_in[1];
    const float* enc    = (const float*)d_in[2];
    const int*   ids    = (const int*)  d_in[3];
    int ei = (in_sizes[4] <= 16) ? 5 : 4;
    const float* emb   = (const float*)d_in[ei + 0];
    const float* w_ih  = (const float*)d_in[ei + 1];
    const float* w_hh  = (const float*)d_in[ei + 2];
    const float* b_ih  = (const float*)d_in[ei + 3];
    const float* b_hh  = (const float*)d_in[ei + 4];
    const float* w_gen = (const float*)d_in[ei + 5];
    const float* b_gen = (const float*)d_in[ei + 6];
    float* out = (float*)d_out;

    const int SMEM3 = SBUF * 2 * 2;  // 51200 bytes
    cudaFuncSetAttribute(k3_kernel, cudaFuncAttributeMaxDynamicSharedMemorySize, SMEM3);
    cudaFuncSetAttribute(k1h_kernel, cudaFuncAttributeMaxDynamicSharedMemorySize, SMEM3);

    init_kernel<<<(Bz * Dd + 255) / 256, 256>>>(hidden);
    bit_kernel<<<Bz, Xx>>>(ids);
    k0e_kernel<<<(int)(((size_t)VP * Dd) / 4096), 256>>>(emb);
    k0w_kernel<<<1728, 256>>>(w_ih, 0);
    k0w_kernel<<<1728, 256>>>(w_hh, 1);
    for (int j = 0; j < Jj; j++) {
        for (int k = 0; k < Kk; k++) {
            int k0 = (k == 0);
            if (k0) k2x_kernel<<<96, 256>>>(dec, j);
            k1h_kernel<<<dim3(18, 2, 2), 256, SMEM3>>>(b_ih, b_hh);
            k2ah_kernel<<<96, 256>>>();
            k2b_kernel<<<dim3(8, Bz), 256>>>(enc, ids);
            k2d_kernel<<<dim3(6, Bz), 128>>>(enc);
            k3_kernel<<<NB, 256, SMEM3>>>();
            k4_kernel<<<Bz, 256>>>(emb, ids, dec, w_gen, b_gen, out, j, k, k0);
            k5w_kernel<<<dim3(30, Bz), 256>>>(out, j, k);
        }
    }
}

// round 12
// speedup vs baseline: 6.5834x; 1.2284x over previous
#include <cuda_runtime.h>
#include <cuda_bf16.h>
#include <math.h>

#define Bz 32
#define Dd 768
#define D3 2304
#define Xx 256
#define VV 30522
#define VP 30720          // 240*128 padded vocab
#define NB 240            // K3 grid (v-blocks of 128)
#define BW 960
#define Jj 4
#define Kk 8
#define NCH 24            // K3 k-chunks of 32
#define NCHH 12           // k1h k-chunks per z-half
// smem element offsets (bf16 elems), rows padded to 40 (80B, conflict-free)
#define SA_H 0
#define SA_L 5120
#define SH_H 10240
#define SH_L 11520
#define SBUF 12800        // elems per buffer (25600 B)

// ---------------- persistent device scratch ----------------
__device__ float g_h[Bz * Dd];
__device__ float g_x[Bz * Dd];
__device__ float g_ctx[Bz * Dd];
__device__ float g_giT[D3 * Bz];    // gate partials, k-half 0 (with bias)
__device__ float g_giT2[D3 * Bz];   // k-half 1
__device__ float g_ghT[D3 * Bz];
__device__ float g_ghT2[D3 * Bz];
__device__ float g_attn[Bz * Xx];    // raw masked scores
__device__ float g_attn_n[Bz * Xx];  // normalized attn
__device__ float g_pgen[Bz];
__device__ float g_inv[Bz];
__device__ __align__(16) float g_e[Bz * VP];
__device__ float g_psum[Bz * NB];
__device__ unsigned long long g_pkey[Bz * NB];
__device__ unsigned int g_bit[Bz * BW];
// split-bf16 emb [VP][768]
__device__ __align__(16) __nv_bfloat16 g_ebh[(size_t)VP * Dd];
__device__ __align__(16) __nv_bfloat16 g_ebl[(size_t)VP * Dd];
// split-bf16 weights [2304][768]
__device__ __align__(16) __nv_bfloat16 g_wih_h[(size_t)D3 * Dd];
__device__ __align__(16) __nv_bfloat16 g_wih_l[(size_t)D3 * Dd];
__device__ __align__(16) __nv_bfloat16 g_whh_h[(size_t)D3 * Dd];
__device__ __align__(16) __nv_bfloat16 g_whh_l[(size_t)D3 * Dd];
// split-bf16 h and x [32][768]
__device__ __align__(16) __nv_bfloat16 g_hhb[Bz * Dd];
__device__ __align__(16) __nv_bfloat16 g_hlb[Bz * Dd];
__device__ __align__(16) __nv_bfloat16 g_xhb[Bz * Dd];
__device__ __align__(16) __nv_bfloat16 g_xlb[Bz * Dd];

__device__ __forceinline__ float sigf(float x) { return 1.0f / (1.0f + expf(-x)); }

__device__ __forceinline__ unsigned int s2u(const void* p) {
    unsigned int a;
    asm("{ .reg .u64 t; cvta.to.shared.u64 t, %1; cvt.u32.u64 %0, t; }" : "=r"(a) : "l"(p));
    return a;
}
__device__ __forceinline__ void cpa16(unsigned int d, const void* s) {
    asm volatile("cp.async.cg.shared.global [%0], [%1], 16;" :: "r"(d), "l"(s) : "memory");
}
__device__ __forceinline__ void mma_bf16(float* d, unsigned a0, unsigned a1,
                                         unsigned a2, unsigned a3,
                                         unsigned b0, unsigned b1) {
    asm volatile(
        "mma.sync.aligned.m16n8k16.row.col.f32.bf16.bf16.f32 "
        "{%0,%1,%2,%3}, {%4,%5,%6,%7}, {%8,%9}, {%0,%1,%2,%3};"
        : "+f"(d[0]), "+f"(d[1]), "+f"(d[2]), "+f"(d[3])
        : "r"(a0), "r"(a1), "r"(a2), "r"(a3), "r"(b0), "r"(b1));
}

// ---------------- init ----------------
__global__ void init_kernel(const float* __restrict__ hidden) {
    int i = blockIdx.x * 256 + threadIdx.x;
    if (i < Bz * Dd) {
        float x = hidden[i];
        g_h[i] = x;
        __nv_bfloat16 hi = __float2bfloat16(x);
        g_hhb[i] = hi;
        g_hlb[i] = __float2bfloat16(x - __bfloat162float(hi));
    }
}
__global__ void bit_kernel(const int* __restrict__ ids) {
    int b = blockIdx.x, t = threadIdx.x;
    int id = ids[b * Xx + t];
    atomicOr(&g_bit[b * BW + (id >> 5)], 1u << (id & 31));
}
// emb -> split bf16 row-major. grid 5760, block 256; 16 elems/thread.
__global__ void k0e_kernel(const float* __restrict__ emb) {
    size_t base = ((size_t)blockIdx.x * 256 + threadIdx.x) * 16;
    int v = (int)(base / Dd);
    bool valid = v < VV;
    const float* src = emb + base;
    #pragma unroll
    for (int i = 0; i < 4; i++) {
        float4 f = valid ? *(const float4*)(src + i * 4) : make_float4(0.f, 0.f, 0.f, 0.f);
        float vs[4] = {f.x, f.y, f.z, f.w};
        #pragma unroll
        for (int u = 0; u < 4; u++) {
            __nv_bfloat16 hi = __float2bfloat16(vs[u]);
            __nv_bfloat16 lo = __float2bfloat16(vs[u] - __bfloat162float(hi));
            g_ebh[base + i * 4 + u] = hi;
            g_ebl[base + i * 4 + u] = lo;
        }
    }
}
// weights -> split bf16. grid 1728, block 256, 4 elems/thread. which: 0=ih, 1=hh.
__global__ void k0w_kernel(const float* __restrict__ w, int which) {
    size_t base = ((size_t)blockIdx.x * 256 + threadIdx.x) * 4;
    __nv_bfloat16* oh = which ? g_whh_h : g_wih_h;
    __nv_bfloat16* ol = which ? g_whh_l : g_wih_l;
    float4 f = *(const float4*)(w + base);
    float vs[4] = {f.x, f.y, f.z, f.w};
    #pragma unroll
    for (int u = 0; u < 4; u++) {
        __nv_bfloat16 hi = __float2bfloat16(vs[u]);
        __nv_bfloat16 lo = __float2bfloat16(vs[u] - __bfloat162float(hi));
        oh[base + u] = hi;
        ol[base + u] = lo;
    }
}

// ---------------- K2x: x -> split bf16 from dec (k==0 steps only) ----------------
__global__ void k2x_kernel(const float* __restrict__ dec, int j) {
    int i = blockIdx.x * 256 + threadIdx.x;   // i = b*Dd + d
    int b = i / Dd, d = i - b * Dd;
    float x = dec[((size_t)b * Jj + j) * Dd + d];
    __nv_bfloat16 hi = __float2bfloat16(x);
    g_xhb[i] = hi;
    g_xlb[i] = __float2bfloat16(x - __bfloat162float(hi));
}

// ---------------- K1h: HMMA gate GEMM half; which: 0=ih(x), 1=hh(h) --------------
// grid (18, 2): x = v-tile, y = K-half. block 256, dyn smem 51200B.
__global__ void __launch_bounds__(256, 2) k1h_kernel(const float* __restrict__ bias,
                                                     int which) {
    extern __shared__ __align__(16) __nv_bfloat16 sm[];
    int t = threadIdx.x, w = t >> 5, lane = t & 31;
    int q = lane & 3, r8 = lane >> 2;
    int vbase = blockIdx.x << 7;
    int z = blockIdx.y;
    int ko0 = z * (NCHH * 32);
    unsigned int sbase = s2u(sm);

    const __nv_bfloat16 *Wh, *Wl, *Bh, *Bl;
    float* OT;
    if (which == 0) {
        Wh = g_wih_h; Wl = g_wih_l; Bh = g_xhb; Bl = g_xlb;
        OT = z ? g_giT2 : g_giT;
    } else {
        Wh = g_whh_h; Wl = g_whh_l; Bh = g_hhb; Bl = g_hlb;
        OT = z ? g_ghT2 : g_ghT;
    }

    float acc[4][4];
    #pragma unroll
    for (int nt = 0; nt < 4; nt++)
        #pragma unroll
        for (int i = 0; i < 4; i++) acc[nt][i] = 0.f;

    int lr = t >> 2, lc = (t & 3) * 8;
    int hr = (t & 127) >> 2, hc = ((t & 127) & 3) * 8;
    const __nv_bfloat16* gA0h = Wh + (size_t)(vbase + lr) * Dd + lc + ko0;
    const __nv_bfloat16* gA1h = Wh + (size_t)(vbase + lr + 64) * Dd + lc + ko0;
    const __nv_bfloat16* gA0l = Wl + (size_t)(vbase + lr) * Dd + lc + ko0;
    const __nv_bfloat16* gA1l = Wl + (size_t)(vbase + lr + 64) * Dd + lc + ko0;
    const __nv_bfloat16* gH = (t < 128 ? Bh : Bl) + (size_t)hr * Dd + hc + ko0;
    unsigned int dA0 = (unsigned)((SA_H + lr * 40 + lc) * 2);
    unsigned int dA1 = (unsigned)((SA_H + (lr + 64) * 40 + lc) * 2);
    unsigned int dL0 = (unsigned)((SA_L + lr * 40 + lc) * 2);
    unsigned int dL1 = (unsigned)((SA_L + (lr + 64) * 40 + lc) * 2);
    unsigned int dH = (unsigned)(((t < 128 ? SH_H : SH_L) + hr * 40 + hc) * 2);

    {
        cpa16(sbase + dA0, gA0h);
        cpa16(sbase + dA1, gA1h);
        cpa16(sbase + dL0, gA0l);
        cpa16(sbase + dL1, gA1l);
        cpa16(sbase + dH, gH);
        asm volatile("cp.async.commit_group;" ::: "memory");
        asm volatile("cp.async.wait_group 0;" ::: "memory");
    }
    __syncthreads();

    for (int kc = 0; kc < NCHH; kc++) {
        int buf = kc & 1;
        if (kc + 1 < NCHH) {
            unsigned int nb = sbase + (buf ^ 1) * (SBUF * 2);
            int ko = (kc + 1) * 32;
            cpa16(nb + dA0, gA0h + ko);
            cpa16(nb + dA1, gA1h + ko);
            cpa16(nb + dL0, gA0l + ko);
            cpa16(nb + dL1, gA1l + ko);
            cpa16(nb + dH, gH + ko);
            asm volatile("cp.async.commit_group;" ::: "memory");
        }
        const __nv_bfloat16* Ah = sm + buf * SBUF + SA_H;
        const __nv_bfloat16* Al = sm + buf * SBUF + SA_L;
        const __nv_bfloat16* Hh = sm + buf * SBUF + SH_H;
        const __nv_bfloat16* Hl = sm + buf * SBUF + SH_L;
        int ar = w * 16 + r8;
        #pragma unroll
        for (int s = 0; s < 2; s++) {
            int k0 = s * 16, ac = k0 + q * 2;
            unsigned ah0 = *(const unsigned*)&Ah[ar * 40 + ac];
            unsigned ah1 = *(const unsigned*)&Ah[(ar + 8) * 40 + ac];
            unsigned ah2 = *(const unsigned*)&Ah[ar * 40 + ac + 8];
            unsigned ah3 = *(const unsigned*)&Ah[(ar + 8) * 40 + ac + 8];
            unsigned al0 = *(const unsigned*)&Al[ar * 40 + ac];
            unsigned al1 = *(const unsigned*)&Al[(ar + 8) * 40 + ac];
            unsigned al2 = *(const unsigned*)&Al[ar * 40 + ac + 8];
            unsigned al3 = *(const unsigned*)&Al[(ar + 8) * 40 + ac + 8];
            #pragma unroll
            for (int nt = 0; nt < 4; nt++) {
                int bn = (nt * 8 + r8) * 40 + k0 + q * 2;
                unsigned bh0 = *(const unsigned*)&Hh[bn];
                unsigned bh1 = *(const unsigned*)&Hh[bn + 8];
                unsigned bl0 = *(const unsigned*)&Hl[bn];
                unsigned bl1 = *(const unsigned*)&Hl[bn + 8];
                mma_bf16(acc[nt], ah0, ah1, ah2, ah3, bh0, bh1);
                mma_bf16(acc[nt], al0, al1, al2, al3, bh0, bh1);
                mma_bf16(acc[nt], ah0, ah1, ah2, ah3, bl0, bl1);
            }
        }
        if (kc + 1 < NCHH)
            asm volatile("cp.async.wait_group 0;" ::: "memory");
        __syncthreads();
    }

    int v0 = vbase + w * 16 + r8, v1 = v0 + 8;
    float bi0 = z ? 0.f : bias[v0];
    float bi1 = z ? 0.f : bias[v1];
    #pragma unroll
    for (int nt = 0; nt < 4; nt++) {
        int b0 = nt * 8 + q * 2, b1 = b0 + 1;
        OT[(size_t)v0 * 32 + b0] = acc[nt][0] + bi0;
        OT[(size_t)v0 * 32 + b1] = acc[nt][1] + bi0;
        OT[(size_t)v1 * 32 + b0] = acc[nt][2] + bi1;
        OT[(size_t)v1 * 32 + b1] = acc[nt][3] + bi1;
    }
}

// ---------------- K2ah: GRU h-update (sums k-halves) + bf16 split ----------------
__global__ void k2ah_kernel() {
    int i = blockIdx.x * 256 + threadIdx.x;
    int d = i >> 5, b = i & 31;
    float gi0 = g_giT[i] + g_giT2[i];
    float gh0 = g_ghT[i] + g_ghT2[i];
    float gi1 = g_giT[(Dd << 5) + i] + g_giT2[(Dd << 5) + i];
    float gh1 = g_ghT[(Dd << 5) + i] + g_ghT2[(Dd << 5) + i];
    float gi2 = g_giT[(2 * Dd << 5) + i] + g_giT2[(2 * Dd << 5) + i];
    float gh2 = g_ghT[(2 * Dd << 5) + i] + g_ghT2[(2 * Dd << 5) + i];
    float r = sigf(gi0 + gh0);
    float z = sigf(gi1 + gh1);
    float n = tanhf(gi2 + r * gh2);
    int hi_ = b * Dd + d;
    float h = (1.f - z) * n + z * g_h[hi_];
    g_h[hi_] = h;
    __nv_bfloat16 hh = __float2bfloat16(h);
    g_hhb[hi_] = hh;
    g_hlb[hi_] = __float2bfloat16(h - __bfloat162float(hh));
}

// ---------------- K2b: attention scores (raw, masked) ----------------
__global__ void k2b_kernel(const float* __restrict__ enc, const int* __restrict__ ids) {
    __shared__ float hs[Dd];
    int b = blockIdx.y, xc = blockIdx.x;
    int t = threadIdx.x, lane = t & 31, w = t >> 5;
    for (int d = t; d < Dd; d += 256) hs[d] = g_h[(size_t)b * Dd + d];
    __syncthreads();
    #pragma unroll
    for (int i = 0; i < 4; i++) {
        int xi = xc * 32 + w * 4 + i;
        const float* er = enc + ((size_t)b * Xx + xi) * Dd;
        float s = 0.f;
        #pragma unroll
        for (int kk = 0; kk < 6; kk++) {
            float4 e4 = *(const float4*)(er + kk * 128 + lane * 4);
            float4 h4 = *(const float4*)(hs + kk * 128 + lane * 4);
            s += e4.x * h4.x + e4.y * h4.y + e4.z * h4.z + e4.w * h4.w;
        }
        #pragma unroll
        for (int o = 16; o; o >>= 1) s += __shfl_xor_sync(0xffffffffu, s, o);
        if (lane == 0)
            g_attn[b * Xx + xi] = (ids[b * Xx + xi] == 0) ? -1e9f : s;
    }
}

// ---------------- K2d: local softmax + context = attn @ enc ----------------
__global__ void k2d_kernel(const float* __restrict__ enc) {
    __shared__ float sc[Xx];
    __shared__ float s_at[Xx];
    __shared__ float red[128];
    int b = blockIdx.y, t = threadIdx.x;
    int d0 = blockIdx.x * 128;
    sc[t] = g_attn[b * Xx + t];
    sc[t + 128] = g_attn[b * Xx + t + 128];
    __syncthreads();
    red[t] = fmaxf(sc[t], sc[t + 128]);
    __syncthreads();
    for (int s2 = 64; s2; s2 >>= 1) { if (t < s2) red[t] = fmaxf(red[t], red[t + s2]); __syncthreads(); }
    float m = red[0];
    __syncthreads();
    float e0 = expf(sc[t] - m), e1 = expf(sc[t + 128] - m);
    red[t] = e0 + e1;
    __syncthreads();
    for (int s2 = 64; s2; s2 >>= 1) { if (t < s2) red[t] += red[t + s2]; __syncthreads(); }
    float inv = 1.f / red[0];
    float a0_ = e0 * inv, a1_ = e1 * inv;
    s_at[t] = a0_;
    s_at[t + 128] = a1_;
    if (blockIdx.x == 0) {
        g_attn_n[b * Xx + t] = a0_;
        g_attn_n[b * Xx + t + 128] = a1_;
    }
    __syncthreads();
    const float* eb = enc + (size_t)b * Xx * Dd + d0 + t;
    float a0 = 0.f, a1 = 0.f, a2 = 0.f, a3 = 0.f;
    #pragma unroll 2
    for (int x = 0; x < Xx; x += 4) {
        a0 += s_at[x + 0] * eb[(size_t)(x + 0) * Dd];
        a1 += s_at[x + 1] * eb[(size_t)(x + 1) * Dd];
        a2 += s_at[x + 2] * eb[(size_t)(x + 2) * Dd];
        a3 += s_at[x + 3] * eb[(size_t)(x + 3) * Dd];
    }
    g_ctx[(size_t)b * Dd + d0 + t] = (a0 + a1) + (a2 + a3);
}

// ---------------- K3: HMMA split-bf16 GEMM, e = exp(emb @ h^T) ----------------
__global__ void __launch_bounds__(256, 2) k3_kernel() {
    extern __shared__ __align__(16) __nv_bfloat16 sm[];
    __shared__ float sSum[8][32];
    __shared__ unsigned long long sKey[8][32];
    int t = threadIdx.x, w = t >> 5, lane = t & 31;
    int q = lane & 3, r8 = lane >> 2;
    int blk = blockIdx.x, vbase = blk << 7;
    unsigned int sbase = s2u(sm);

    float acc[4][4];
    #pragma unroll
    for (int nt = 0; nt < 4; nt++)
        #pragma unroll
        for (int i = 0; i < 4; i++) acc[nt][i] = 0.f;

    int lr = t >> 2, lc = (t & 3) * 8;
    int hr = (t & 127) >> 2, hc = ((t & 127) & 3) * 8;
    const __nv_bfloat16* gA0h = g_ebh + (size_t)(vbase + lr) * Dd + lc;
    const __nv_bfloat16* gA1h = g_ebh + (size_t)(vbase + lr + 64) * Dd + lc;
    const __nv_bfloat16* gA0l = g_ebl + (size_t)(vbase + lr) * Dd + lc;
    const __nv_bfloat16* gA1l = g_ebl + (size_t)(vbase + lr + 64) * Dd + lc;
    const __nv_bfloat16* gH = (t < 128 ? g_hhb : g_hlb) + (size_t)hr * Dd + hc;
    unsigned int dA0 = (unsigned)((SA_H + lr * 40 + lc) * 2);
    unsigned int dA1 = (unsigned)((SA_H + (lr + 64) * 40 + lc) * 2);
    unsigned int dL0 = (unsigned)((SA_L + lr * 40 + lc) * 2);
    unsigned int dL1 = (unsigned)((SA_L + (lr + 64) * 40 + lc) * 2);
    unsigned int dH = (unsigned)(((t < 128 ? SH_H : SH_L) + hr * 40 + hc) * 2);

    {
        cpa16(sbase + dA0, gA0h);
        cpa16(sbase + dA1, gA1h);
        cpa16(sbase + dL0, gA0l);
        cpa16(sbase + dL1, gA1l);
        cpa16(sbase + dH, gH);
        asm volatile("cp.async.commit_group;" ::: "memory");
        asm volatile("cp.async.wait_group 0;" ::: "memory");
    }
    __syncthreads();

    for (int kc = 0; kc < NCH; kc++) {
        int buf = kc & 1;
        if (kc + 1 < NCH) {
            unsigned int nb = sbase + (buf ^ 1) * (SBUF * 2);
            int ko = (kc + 1) * 32;
            cpa16(nb + dA0, gA0h + ko);
            cpa16(nb + dA1, gA1h + ko);
            cpa16(nb + dL0, gA0l + ko);
            cpa16(nb + dL1, gA1l + ko);
            cpa16(nb + dH, gH + ko);
            asm volatile("cp.async.commit_group;" ::: "memory");
        }
        const __nv_bfloat16* Ah = sm + buf * SBUF + SA_H;
        const __nv_bfloat16* Al = sm + buf * SBUF + SA_L;
        const __nv_bfloat16* Hh = sm + buf * SBUF + SH_H;
        const __nv_bfloat16* Hl = sm + buf * SBUF + SH_L;
        int ar = w * 16 + r8;
        #pragma unroll
        for (int s = 0; s < 2; s++) {
            int k0 = s * 16, ac = k0 + q * 2;
            unsigned ah0 = *(const unsigned*)&Ah[ar * 40 + ac];
            unsigned ah1 = *(const unsigned*)&Ah[(ar + 8) * 40 + ac];
            unsigned ah2 = *(const unsigned*)&Ah[ar * 40 + ac + 8];
            unsigned ah3 = *(const unsigned*)&Ah[(ar + 8) * 40 + ac + 8];
            unsigned al0 = *(const unsigned*)&Al[ar * 40 + ac];
            unsigned al1 = *(const unsigned*)&Al[(ar + 8) * 40 + ac];
            unsigned al2 = *(const unsigned*)&Al[ar * 40 + ac + 8];
            unsigned al3 = *(const unsigned*)&Al[(ar + 8) * 40 + ac + 8];
            #pragma unroll
            for (int nt = 0; nt < 4; nt++) {
                int bn = (nt * 8 + r8) * 40 + k0 + q * 2;
                unsigned bh0 = *(const unsigned*)&Hh[bn];
                unsigned bh1 = *(const unsigned*)&Hh[bn + 8];
                unsigned bl0 = *(const unsigned*)&Hl[bn];
                unsigned bl1 = *(const unsigned*)&Hl[bn + 8];
                mma_bf16(acc[nt], ah0, ah1, ah2, ah3, bh0, bh1);
                mma_bf16(acc[nt], al0, al1, al2, al3, bh0, bh1);
                mma_bf16(acc[nt], ah0, ah1, ah2, ah3, bl0, bl1);
            }
        }
        if (kc + 1 < NCH)
            asm volatile("cp.async.wait_group 0;" ::: "memory");
        __syncthreads();
    }

    int v0 = vbase + w * 16 + r8, v1 = v0 + 8;
    bool ok0 = v0 < VV, ok1 = v1 < VV;
    #pragma unroll
    for (int nt = 0; nt < 4; nt++) {
        float e00 = ok0 ? __expf(acc[nt][0]) : 0.f;
        float e01 = ok0 ? __expf(acc[nt][1]) : 0.f;
        float e10 = ok1 ? __expf(acc[nt][2]) : 0.f;
        float e11 = ok1 ? __expf(acc[nt][3]) : 0.f;
        int b0 = nt * 8 + q * 2, b1 = b0 + 1;
        g_e[(size_t)b0 * VP + v0] = e00;
        g_e[(size_t)b1 * VP + v0] = e01;
        g_e[(size_t)b0 * VP + v1] = e10;
        g_e[(size_t)b1 * VP + v1] = e11;
        float s0 = e00 + e10, s1 = e01 + e11;
        unsigned long long k00 = ((unsigned long long)__float_as_uint(e00) << 32) | (unsigned)(~v0);
        unsigned long long k10 = ((unsigned long long)__float_as_uint(e10) << 32) | (unsigned)(~v1);
        unsigned long long k01 = ((unsigned long long)__float_as_uint(e01) << 32) | (unsigned)(~v0);
        unsigned long long k11 = ((unsigned long long)__float_as_uint(e11) << 32) | (unsigned)(~v1);
        unsigned long long key0 = k00 > k10 ? k00 : k10;
        unsigned long long key1 = k01 > k11 ? k01 : k11;
        #pragma unroll
        for (int o = 4; o <= 16; o <<= 1) {
            s0 += __shfl_xor_sync(0xffffffffu, s0, o);
            s1 += __shfl_xor_sync(0xffffffffu, s1, o);
            unsigned long long t0 = __shfl_xor_sync(0xffffffffu, key0, o);
            unsigned long long t1 = __shfl_xor_sync(0xffffffffu, key1, o);
            if (t0 > key0) key0 = t0;
            if (t1 > key1) key1 = t1;
        }
        if (r8 == 0) {
            sSum[w][b0] = s0; sSum[w][b1] = s1;
            sKey[w][b0] = key0; sKey[w][b1] = key1;
        }
    }
    __syncthreads();
    if (t < 32) {
        float s = 0.f;
        unsigned long long k = 0ull;
        #pragma unroll
        for (int w2 = 0; w2 < 8; w2++) {
            s += sSum[w2][t];
            if (sKey[w2][t] > k) k = sKey[w2][t];
        }
        g_psum[t * NB + blk] = s;
        g_pkey[t * NB + blk] = k;
    }
}

// ---------------- K4: p_gen; reduce partials; scatter; argmax; x_next (+split) ----
__global__ void k4_kernel(const float* __restrict__ emb, const int* __restrict__ ids,
                          const float* __restrict__ dec,
                          const float* __restrict__ w_gen, const float* __restrict__ b_gen,
                          float* __restrict__ out, int j, int kstep, int k0) {
    __shared__ float rf[256];
    __shared__ unsigned long long rk[256];
    __shared__ float s_at[Xx];
    __shared__ int s_ids[Xx];
    __shared__ int s_am;
    __shared__ float s_pg;
    int b = blockIdx.x, t = threadIdx.x;

    const float* xr = k0 ? (dec + ((size_t)b * Jj + j) * Dd) : (g_x + (size_t)b * Dd);
    float pgp = 0.f;
    for (int d = t; d < Dd; d += 256)
        pgp += w_gen[d] * g_h[(size_t)b * Dd + d]
             + w_gen[Dd + d] * xr[d]
             + w_gen[2 * Dd + d] * g_ctx[(size_t)b * Dd + d];
    rf[t] = pgp; __syncthreads();
    for (int s2 = 128; s2; s2 >>= 1) { if (t < s2) rf[t] += rf[t + s2]; __syncthreads(); }
    if (t == 0) { s_pg = sigf(rf[0] + b_gen[0]); g_pgen[b] = s_pg; }
    __syncthreads();
    float pg = s_pg;
    __syncthreads();

    rf[t] = (t < NB) ? g_psum[b * NB + t] : 0.f;
    rk[t] = (t < NB) ? g_pkey[b * NB + t] : 0ull;
    s_ids[t] = ids[b * Xx + t];
    s_at[t] = g_attn_n[b * Xx + t];
    __syncthreads();
    for (int s2 = 128; s2; s2 >>= 1) {
        if (t < s2) {
            rf[t] += rf[t + s2];
            if (rk[t + s2] > rk[t]) rk[t] = rk[t + s2];
        }
        __syncthreads();
    }
    float inv = 1.f / rf[0];
    int vd = ~(unsigned)(rk[0] & 0xffffffffu);
    if (t == 0) g_inv[b] = inv;
    __syncthreads();

    const float* erow = g_e + (size_t)b * VP;
    float* orow = out + (((size_t)b * Jj + j) * Kk + kstep) * VV;
    float one_m = 1.f - pg;

    float dval = pg * erow[vd] * inv;
    unsigned long long best =
        ((unsigned long long)__float_as_uint(dval) << 32) | (unsigned)(~vd);
    {
        int v = s_ids[t];
        float a = 0.f;
        #pragma unroll 4
        for (int x2 = 0; x2 < Xx; x2++) a += (s_ids[x2] == v) ? s_at[x2] : 0.f;
        float full = pg * erow[v] * inv + one_m * a;
        orow[v] = full;
        unsigned long long key =
            ((unsigned long long)__float_as_uint(full) << 32) | (unsigned)(~v);
        if (key > best) best = key;
    }
    rk[t] = best; __syncthreads();
    for (int s2 = 128; s2; s2 >>= 1) {
        if (t < s2 && rk[t + s2] > rk[t]) rk[t] = rk[t + s2];
        __syncthreads();
    }
    if (t == 0) s_am = ~(unsigned)(rk[0] & 0xffffffffu);
    __syncthreads();
    int am = s_am;
    for (int d = t; d < Dd; d += 256) {
        float xv = emb[(size_t)am * Dd + d];
        int xi = b * Dd + d;
        g_x[xi] = xv;
        __nv_bfloat16 hi = __float2bfloat16(xv);
        g_xhb[xi] = hi;
        g_xlb[xi] = __float2bfloat16(xv - __bfloat162float(hi));
    }
}

// ---------------- K5w: dense output write ----------------
__global__ void k5w_kernel(float* __restrict__ out, int j, int kstep) {
    int b = blockIdx.y, t = threadIdx.x;
    int v0 = blockIdx.x * 1024 + t * 4;
    if (v0 >= VV) return;
    float sc = g_pgen[b] * g_inv[b];
    const float* erow = g_e + (size_t)b * VP;
    float* orow = out + (((size_t)b * Jj + j) * Kk + kstep) * VV;
    unsigned m = (g_bit[b * BW + (v0 >> 5)] >> (v0 & 31)) & 0xFu;
    if (v0 + 3 < VV) {
        float4 e4 = *(const float4*)(erow + v0);
        float o0 = sc * e4.x, o1 = sc * e4.y, o2 = sc * e4.z, o3 = sc * e4.w;
        if (m == 0u) {
            *(float2*)(orow + v0)     = make_float2(o0, o1);
            *(float2*)(orow + v0 + 2) = make_float2(o2, o3);
        } else {
            if (!(m & 1u)) orow[v0 + 0] = o0;
            if (!(m & 2u)) orow[v0 + 1] = o1;
            if (!(m & 4u)) orow[v0 + 2] = o2;
            if (!(m & 8u)) orow[v0 + 3] = o3;
        }
    } else {
        for (int v = v0; v < VV; v++)
            if (!((m >> (v - v0)) & 1u)) orow[v] = sc * erow[v];
    }
}

extern "C" void kernel_launch(void* const* d_in, const int* in_sizes, int n_in,
                              void* d_out, int out_size) {
    const float* dec    = (const float*)d_in[0];
    const float* hidden = (const float*)d_in[1];
    const float* enc    = (const float*)d_in[2];
    const int*   ids    = (const int*)  d_in[3];
    int ei = (in_sizes[4] <= 16) ? 5 : 4;
    const float* emb   = (const float*)d_in[ei + 0];
    const float* w_ih  = (const float*)d_in[ei + 1];
    const float* w_hh  = (const float*)d_in[ei + 2];
    const float* b_ih  = (const float*)d_in[ei + 3];
    const float* b_hh  = (const float*)d_in[ei + 4];
    const float* w_gen = (const float*)d_in[ei + 5];
    const float* b_gen = (const float*)d_in[ei + 6];
    float* out = (float*)d_out;

    const int SMEM3 = SBUF * 2 * 2;  // 51200 bytes
    cudaFuncSetAttribute(k3_kernel, cudaFuncAttributeMaxDynamicSharedMemorySize, SMEM3);
    cudaFuncSetAttribute(k1h_kernel, cudaFuncAttributeMaxDynamicSharedMemorySize, SMEM3);

    // side stream + events (fork/join pattern valid under stream capture;
    // host-side objects only — no device allocations). Not destroyed here:
    // destroying a stream mid-capture would invalidate the capture.
    cudaStream_t s2;
    cudaStreamCreateWithFlags(&s2, cudaStreamNonBlocking);
    cudaEvent_t evH, evJoinH, ev3, ev4, evEnd;
    cudaEventCreateWithFlags(&evH,     cudaEventDisableTiming);
    cudaEventCreateWithFlags(&evJoinH, cudaEventDisableTiming);
    cudaEventCreateWithFlags(&ev3,     cudaEventDisableTiming);
    cudaEventCreateWithFlags(&ev4,     cudaEventDisableTiming);
    cudaEventCreateWithFlags(&evEnd,   cudaEventDisableTiming);

    // ---- prologue (main) ----
    init_kernel<<<(Bz * Dd + 255) / 256, 256>>>(hidden);
    bit_kernel<<<Bz, Xx>>>(ids);
    k0e_kernel<<<(int)(((size_t)VP * Dd) / 4096), 256>>>(emb);
    k0w_kernel<<<1728, 256>>>(w_ih, 0);
    k0w_kernel<<<1728, 256>>>(w_hh, 1);
    cudaEventRecord(evH, 0);
    // side: hh-GEMM for step 0 (needs initial g_hhb)
    cudaStreamWaitEvent(s2, evH, 0);
    k1h_kernel<<<dim3(18, 2), 256, SMEM3, s2>>>(b_hh, 1);
    cudaEventRecord(evJoinH, s2);
    // main: x for step 0 + ih-GEMM
    k2x_kernel<<<96, 256>>>(dec, 0);
    k1h_kernel<<<dim3(18, 2), 256, SMEM3>>>(b_ih, 0);

    for (int s = 0; s < Jj * Kk; s++) {
        int j = s >> 3, k = s & 7;
        int k0 = (k == 0);
        // seg1 (main): h update
        cudaStreamWaitEvent(0, evJoinH, 0);
        k2ah_kernel<<<96, 256>>>();
        cudaEventRecord(evH, 0);
        // seg2 (side): vocab GEMM, then next step's hh-GEMM
        cudaStreamWaitEvent(s2, evH, 0);
        k3_kernel<<<NB, 256, SMEM3, s2>>>();
        cudaEventRecord(ev3, s2);
        if (s + 1 < Jj * Kk) {
            k1h_kernel<<<dim3(18, 2), 256, SMEM3, s2>>>(b_hh, 1);
            cudaEventRecord(evJoinH, s2);
        }
        // seg3 (main): attention path, then join + k4, then next step's x/ih-GEMM
        k2b_kernel<<<dim3(8, Bz), 256>>>(enc, ids);
        k2d_kernel<<<dim3(6, Bz), 128>>>(enc);
        cudaStreamWaitEvent(0, ev3, 0);
        k4_kernel<<<Bz, 256>>>(emb, ids, dec, w_gen, b_gen, out, j, k, k0);
        cudaEventRecord(ev4, 0);
        if (s + 1 < Jj * Kk) {
            if (((s + 1) & 7) == 0) k2x_kernel<<<96, 256>>>(dec, (s + 1) >> 3);
            k1h_kernel<<<dim3(18, 2), 256, SMEM3>>>(b_ih, 0);
        }
        // seg4 (side): dense output write (g_e safe: next k3 is later on s2)
        cudaStreamWaitEvent(s2, ev4, 0);
        k5w_kernel<<<dim3(30, Bz), 256, 0, s2>>>(out, j, k);
    }
    // join side stream back into the captured origin stream
    cudaEventRecord(evEnd, s2);
    cudaStreamWaitEvent(0, evEnd, 0);
}